// round 2
// baseline (speedup 1.0000x reference)
#include <cuda_runtime.h>

#define NN   256
#define FIN  6
#define HD   32
#define VECD 26
#define DPI  512
#define BB   1024
#define EMAX 2304
#define ST   36   // padded row stride in floats: 16B-aligned rows, conflict-free columns

__device__ int g_rowptr[NN + 1];
__device__ __align__(16) float2 g_edge[EMAX];  // .x = __int_as_float(col*ST), .y = norm val
__device__ float g_comb[BB * 64];              // [b][0:26]=vec, [26:58]=emb

// ---------------------------------------------------------------------------
// packed f32x2 helpers
// ---------------------------------------------------------------------------
__device__ __forceinline__ unsigned long long dup2(float v) {
    unsigned long long r;
    asm("mov.b64 %0, {%1, %1};" : "=l"(r) : "f"(v));
    return r;
}
__device__ __forceinline__ void ffma2(unsigned long long& a, unsigned long long x,
                                      unsigned long long y) {
    asm("fma.rn.f32x2 %0, %1, %2, %0;" : "+l"(a) : "l"(x), "l"(y));
}

// ---------------------------------------------------------------------------
// Prep: degrees -> symmetric norm, CSR by dst, col pre-scaled to float index.
// ---------------------------------------------------------------------------
__global__ void prep_kernel(const int* __restrict__ src, const int* __restrict__ dst, int E) {
    __shared__ float degO[NN], degI[NN];
    __shared__ int cur[NN];
    int t = threadIdx.x;
    degO[t] = 0.f; degI[t] = 0.f;
    __syncthreads();
    for (int e = t; e < E; e += NN) {
        atomicAdd(&degO[src[e]], 1.f);
        atomicAdd(&degI[dst[e]], 1.f);
    }
    __syncthreads();
    if (t == 0) {
        int acc = 0;
        for (int n = 0; n < NN; n++) {
            g_rowptr[n] = acc; cur[n] = acc;
            acc += (int)degI[n];
        }
        g_rowptr[NN] = acc;
    }
    __syncthreads();
    float io = degO[t] > 0.f ? rsqrtf(degO[t]) : 0.f;
    float ii = degI[t] > 0.f ? rsqrtf(degI[t]) : 0.f;
    __syncthreads();
    degO[t] = io; degI[t] = ii;
    __syncthreads();
    for (int e = t; e < E; e += NN) {
        int s_ = src[e], d_ = dst[e];
        float nv = degO[s_] * degI[d_];
        int pos = atomicAdd(&cur[d_], 1);
        g_edge[pos] = make_float2(__int_as_float(s_ * ST), nv);
    }
}

// ---------------------------------------------------------------------------
// Gather: feature-parallel (lane=feature), node-sequential per warp.
// Warp-uniform edge loop, conflict-free LDS.32 X reads, broadcast CSR reads.
// ---------------------------------------------------------------------------
template <int POOL>
__device__ __forceinline__ void gather_phase(const float* __restrict__ bufS,
                                             float* __restrict__ bufD,
                                             const float2* __restrict__ sE,
                                             const int* __restrict__ srow,
                                             const float* __restrict__ sbias,
                                             float* __restrict__ poolArr, int t)
{
    int lane = t & 31, w = t >> 5;
    float biasv = sbias[lane];
    const float* Xl = bufS + lane;
    int n0 = w * 32;
    int rs = srow[n0];
    float psum = 0.f;
    for (int nn = 0; nn < 32; nn++) {
        int re = srow[n0 + nn + 1];
        float a0 = 0.f, a1 = 0.f, a2 = 0.f, a3 = 0.f;
        int j = rs;
        for (; j + 3 < re; j += 4) {
            float2 e0 = sE[j], e1 = sE[j + 1], e2 = sE[j + 2], e3 = sE[j + 3];
            a0 = fmaf(e0.y, Xl[__float_as_int(e0.x)], a0);
            a1 = fmaf(e1.y, Xl[__float_as_int(e1.x)], a1);
            a2 = fmaf(e2.y, Xl[__float_as_int(e2.x)], a2);
            a3 = fmaf(e3.y, Xl[__float_as_int(e3.x)], a3);
        }
        for (; j < re; j++) {
            float2 e = sE[j];
            a0 = fmaf(e.y, Xl[__float_as_int(e.x)], a0);
        }
        float acc = fmaxf((a0 + a1) + (a2 + a3) + biasv, 0.f);
        if (POOL) psum += acc;
        else bufD[(n0 + nn) * ST + lane] = acc;
        rs = re;
    }
    if (POOL) poolArr[w * 32 + lane] = psum;
}

// ---------------------------------------------------------------------------
// Linear: thread=node, 32x32 matmul via packed fma.rn.f32x2.
// ---------------------------------------------------------------------------
__device__ __forceinline__ void linear_phase(const float* __restrict__ bufS,
                                             float* __restrict__ bufD,
                                             const float* __restrict__ W, int t)
{
    float h[HD];
    const float4* hr = (const float4*)(bufS + t * ST);
#pragma unroll
    for (int q = 0; q < 8; q++) {
        float4 v = hr[q];
        h[4*q] = v.x; h[4*q+1] = v.y; h[4*q+2] = v.z; h[4*q+3] = v.w;
    }
    unsigned long long y2[16];
#pragma unroll
    for (int q = 0; q < 16; q++) y2[q] = 0ULL;
#pragma unroll
    for (int k = 0; k < HD; k++) {
        unsigned long long hk = dup2(h[k]);
        const ulonglong2* Wr = (const ulonglong2*)(W + k * HD);
#pragma unroll
        for (int q = 0; q < 8; q++) {
            ulonglong2 wv = Wr[q];
            ffma2(y2[2*q],     hk, wv.x);
            ffma2(y2[2*q + 1], hk, wv.y);
        }
    }
    ulonglong2* out = (ulonglong2*)(bufD + t * ST);
#pragma unroll
    for (int q = 0; q < 8; q++) out[q] = make_ulonglong2(y2[2*q], y2[2*q+1]);
}

// ---------------------------------------------------------------------------
// Main GNN kernel: one CTA per batch element.
// ---------------------------------------------------------------------------
__global__ void __launch_bounds__(NN, 2) gnn_kernel(
    const float* __restrict__ gf, const float* __restrict__ vec,
    const float* __restrict__ W1, const float* __restrict__ b1,
    const float* __restrict__ W2, const float* __restrict__ b2,
    const float* __restrict__ W3, const float* __restrict__ b3,
    const float* __restrict__ We, const float* __restrict__ be)
{
    extern __shared__ float s[];
    float*  bufA = s;                          // 9216
    float*  bufB = bufA + NN * ST;             // 9216
    float2* sE   = (float2*)(bufB + NN * ST);  // 2304*2 floats
    int*    srow = (int*)(sE + EMAX);          // 260 (padded, keeps 16B align)
    float*  sW1  = (float*)(srow + 260);       // 192
    float*  sW2  = sW1 + 192;                  // 1024
    float*  sW3  = sW2 + 1024;                 // 1024
    float*  sWe  = sW3 + 1024;                 // 1024
    float*  sb   = sWe + 1024;                 // 128 (b1|b2|b3|be)
    float*  pool = sb + 128;                   // 256
    float*  hg   = pool + 256;                 // 32

    int t = threadIdx.x;
    int b = blockIdx.x;

    // ---- stage CSR, weights, gf ----
    {
        const float4* ge4 = (const float4*)g_edge;
        float4* se4 = (float4*)sE;
        for (int i = t; i < EMAX / 2; i += NN) se4[i] = ge4[i];
        srow[t] = g_rowptr[t];
        if (t == 0) srow[NN] = g_rowptr[NN];
        if (t < FIN * HD) sW1[t] = W1[t];
        for (int i = t; i < HD * HD; i += NN) {
            sW2[i] = W2[i]; sW3[i] = W3[i]; sWe[i] = We[i];
        }
        if (t < HD) { sb[t] = b1[t]; sb[32+t] = b2[t]; sb[64+t] = b3[t]; sb[96+t] = be[t]; }
        const float4* g4 = (const float4*)(gf + (size_t)b * NN * FIN);
        float4* xb = (float4*)bufB;
        for (int i = t; i < NN * FIN / 4; i += NN) xb[i] = g4[i];
    }
    __syncthreads();

    // ---- phase 0: t0 = x @ W1 -> bufA (thread = node) ----
    {
        float x[FIN];
#pragma unroll
        for (int k = 0; k < FIN; k++) x[k] = bufB[t * FIN + k];
        unsigned long long y2[16];
#pragma unroll
        for (int q = 0; q < 16; q++) y2[q] = 0ULL;
#pragma unroll
        for (int k = 0; k < FIN; k++) {
            unsigned long long xk = dup2(x[k]);
            const ulonglong2* Wr = (const ulonglong2*)(sW1 + k * HD);
#pragma unroll
            for (int q = 0; q < 8; q++) {
                ulonglong2 wv = Wr[q];
                ffma2(y2[2*q], xk, wv.x);
                ffma2(y2[2*q+1], xk, wv.y);
            }
        }
        ulonglong2* row = (ulonglong2*)(bufA + t * ST);
#pragma unroll
        for (int q = 0; q < 8; q++) row[q] = make_ulonglong2(y2[2*q], y2[2*q+1]);
    }
    __syncthreads();

    // ---- layer 1: gather(bufA) +b1,relu -> bufB ----
    gather_phase<0>(bufA, bufB, sE, srow, sb, pool, t);
    __syncthreads();
    // ---- h1 @ W2 -> bufA ----
    linear_phase(bufB, bufA, sW2, t);
    __syncthreads();
    // ---- layer 2: gather(bufA) +b2,relu -> bufB ----
    gather_phase<0>(bufA, bufB, sE, srow, sb + 32, pool, t);
    __syncthreads();
    // ---- h2 @ W3 -> bufA ----
    linear_phase(bufB, bufA, sW3, t);
    __syncthreads();
    // ---- layer 3: gather(bufA) +b3,relu -> pool partials ----
    gather_phase<1>(bufA, bufB, sE, srow, sb + 64, pool, t);
    __syncthreads();

    // ---- mean pool + embedding + comb write ----
    if (t < HD) {
        float sum = 0.f;
#pragma unroll
        for (int ww = 0; ww < 8; ww++) sum += pool[ww * 32 + t];
        hg[t] = sum * (1.f / 256.f);
    }
    __syncthreads();
    if (t < HD) {
        float e = sb[96 + t];
#pragma unroll
        for (int k = 0; k < HD; k++) e = fmaf(hg[k], sWe[k * HD + t], e);
        g_comb[b * 64 + VECD + t] = e;
    }
    if (t >= 64 && t < 64 + VECD)
        g_comb[b * 64 + (t - 64)] = vec[(size_t)b * VECD + (t - 64)];
}

// ---------------------------------------------------------------------------
// Heads: [1024 x 58] @ [58 x 512] x2, tiled so weights are read ~8x total.
// 128 CTAs x 8 batches; thread t owns cols {t, t+256} of both heads.
// ---------------------------------------------------------------------------
__global__ void __launch_bounds__(NN) heads_kernel(
    const float* __restrict__ Wpi, const float* __restrict__ bpi,
    const float* __restrict__ Wvf, const float* __restrict__ bvf,
    float* __restrict__ out)
{
    __shared__ float sc[8][64];
    int t = threadIdx.x;
    int b0 = blockIdx.x * 8;
    for (int i = t; i < 8 * 64; i += NN)
        sc[i >> 6][i & 63] = g_comb[(size_t)(b0 + (i >> 6)) * 64 + (i & 63)];
    __syncthreads();

    float a0[8], a1[8], a2[8], a3[8];
    float bp0 = bpi[t], bp1 = bpi[t + 256], bv0 = bvf[t], bv1 = bvf[t + 256];
#pragma unroll
    for (int i = 0; i < 8; i++) { a0[i] = bp0; a1[i] = bp1; a2[i] = bv0; a3[i] = bv1; }

#pragma unroll
    for (int k = 0; k < VECD + HD; k++) {
        float w0 = Wpi[k * DPI + t];
        float w1 = Wpi[k * DPI + t + 256];
        float w2 = Wvf[k * DPI + t];
        float w3 = Wvf[k * DPI + t + 256];
#pragma unroll
        for (int i = 0; i < 8; i++) {
            float c = sc[i][k];
            a0[i] = fmaf(w0, c, a0[i]);
            a1[i] = fmaf(w1, c, a1[i]);
            a2[i] = fmaf(w2, c, a2[i]);
            a3[i] = fmaf(w3, c, a3[i]);
        }
    }
#pragma unroll
    for (int i = 0; i < 8; i++) {
        size_t rb = (size_t)(b0 + i) * DPI;
        out[rb + t]                          = fmaxf(a0[i], 0.f);
        out[rb + t + 256]                    = fmaxf(a1[i], 0.f);
        out[(size_t)BB * DPI + rb + t]       = fmaxf(a2[i], 0.f);
        out[(size_t)BB * DPI + rb + t + 256] = fmaxf(a3[i], 0.f);
    }
}

extern "C" void kernel_launch(void* const* d_in, const int* in_sizes, int n_in,
                              void* d_out, int out_size) {
    const float* gf  = (const float*)d_in[0];
    const float* vec = (const float*)d_in[1];
    const int*   src = (const int*)d_in[2];
    const int*   dst = (const int*)d_in[3];
    const float* W1  = (const float*)d_in[4];
    const float* b1  = (const float*)d_in[5];
    const float* W2  = (const float*)d_in[6];
    const float* b2  = (const float*)d_in[7];
    const float* W3  = (const float*)d_in[8];
    const float* b3  = (const float*)d_in[9];
    const float* We  = (const float*)d_in[10];
    const float* be  = (const float*)d_in[11];
    const float* Wpi = (const float*)d_in[12];
    const float* bpi = (const float*)d_in[13];
    const float* Wvf = (const float*)d_in[14];
    const float* bvf = (const float*)d_in[15];

    int E = in_sizes[2];
    if (E > EMAX) E = EMAX;

    prep_kernel<<<1, NN>>>(src, dst, E);

    // smem floats: 2*9216 + 4608 + 260 + 192 + 3*1024 + 128 + 256 + 32 = 26980
    int smem = 26980 * (int)sizeof(float);
    cudaFuncSetAttribute(gnn_kernel, cudaFuncAttributeMaxDynamicSharedMemorySize, smem);
    gnn_kernel<<<BB, NN, smem>>>(gf, vec, W1, b1, W2, b2, W3, b3, We, be);
    heads_kernel<<<BB / 8, NN>>>(Wpi, bpi, Wvf, bvf, (float*)d_out);
}

// round 3
// speedup vs baseline: 1.2737x; 1.2737x over previous
#include <cuda_runtime.h>

#define NN   256
#define FIN  6
#define HD   32
#define VECD 26
#define DPI  512
#define BB   1024
#define EMAX 2304
#define ST   36   // padded row stride in floats: 16B-aligned rows, good bank spread

__device__ int g_rowptr[NN + 1];
__device__ __align__(16) float2 g_edge[EMAX];  // .x = __int_as_float(col*ST), .y = norm
__device__ float g_comb[BB * 64];              // [b][0:26]=vec, [26:58]=emb

// ---------------------------------------------------------------------------
// packed f32x2 helpers
// ---------------------------------------------------------------------------
__device__ __forceinline__ unsigned long long dup2(float v) {
    unsigned long long r;
    asm("mov.b64 %0, {%1, %1};" : "=l"(r) : "f"(v));
    return r;
}
__device__ __forceinline__ void ffma2(unsigned long long& a, unsigned long long x,
                                      unsigned long long y) {
    asm("fma.rn.f32x2 %0, %1, %2, %0;" : "+l"(a) : "l"(x), "l"(y));
}
__device__ __forceinline__ void unpack2(float& lo, float& hi, unsigned long long v) {
    asm("mov.b64 {%0, %1}, %2;" : "=f"(lo), "=f"(hi) : "l"(v));
}

// ---------------------------------------------------------------------------
// Prep: degrees -> symmetric norm, CSR by dst. Parallel prefix scan (shfl).
// ---------------------------------------------------------------------------
__global__ void prep_kernel(const int* __restrict__ src, const int* __restrict__ dst, int E) {
    __shared__ float degO[NN], degI[NN];
    __shared__ int cur[NN];
    __shared__ int wsum[8];
    int t = threadIdx.x, lane = t & 31, w = t >> 5;
    degO[t] = 0.f; degI[t] = 0.f;
    __syncthreads();
    for (int e = t; e < E; e += NN) {
        atomicAdd(&degO[src[e]], 1.f);
        atomicAdd(&degI[dst[e]], 1.f);
    }
    __syncthreads();
    int di = (int)degI[t];
    // warp-level inclusive scan of degrees
    int v = di;
#pragma unroll
    for (int o = 1; o < 32; o <<= 1) {
        int n = __shfl_up_sync(0xffffffffu, v, o);
        if (lane >= o) v += n;
    }
    if (lane == 31) wsum[w] = v;
    __syncthreads();
    if (t == 0) {
        int acc = 0;
#pragma unroll
        for (int i = 0; i < 8; i++) { acc += wsum[i]; wsum[i] = acc; }
    }
    __syncthreads();
    int base = (w > 0) ? wsum[w - 1] : 0;
    int excl = base + v - di;
    g_rowptr[t] = excl;
    cur[t] = excl;
    if (t == NN - 1) g_rowptr[NN] = excl + di;
    float io = degO[t] > 0.f ? rsqrtf(degO[t]) : 0.f;
    float ii = degI[t] > 0.f ? rsqrtf(degI[t]) : 0.f;
    __syncthreads();
    degO[t] = io; degI[t] = ii;
    __syncthreads();
    for (int e = t; e < E; e += NN) {
        int s_ = src[e], d_ = dst[e];
        float nv = degO[s_] * degI[d_];
        int pos = atomicAdd(&cur[d_], 1);
        g_edge[pos] = make_float2(__int_as_float(s_ * ST), nv);
    }
}

// ---------------------------------------------------------------------------
// Gather: thread = node, f32x2-packed accumulation, CSR from smem.
// ---------------------------------------------------------------------------
__device__ __forceinline__ void gather2(const float* __restrict__ bufS,
                                        float* __restrict__ bufD,
                                        const float2* __restrict__ sE,
                                        const int* __restrict__ srow,
                                        const float* __restrict__ sbias, int t)
{
    int rs = srow[t], re = srow[t + 1];
    unsigned long long agg[16];
#pragma unroll
    for (int q = 0; q < 16; q++) agg[q] = 0ULL;
    int j = rs;
    for (; j + 1 < re; j += 2) {
        float2 e0 = sE[j], e1 = sE[j + 1];
        const ulonglong2* r0 = (const ulonglong2*)(bufS + __float_as_int(e0.x));
        const ulonglong2* r1 = (const ulonglong2*)(bufS + __float_as_int(e1.x));
        unsigned long long v0 = dup2(e0.y), v1 = dup2(e1.y);
#pragma unroll
        for (int q = 0; q < 8; q++) {
            ulonglong2 w0 = r0[q];
            ulonglong2 w1 = r1[q];
            ffma2(agg[2*q],     v0, w0.x);
            ffma2(agg[2*q + 1], v0, w0.y);
            ffma2(agg[2*q],     v1, w1.x);
            ffma2(agg[2*q + 1], v1, w1.y);
        }
    }
    if (j < re) {
        float2 e0 = sE[j];
        const ulonglong2* r0 = (const ulonglong2*)(bufS + __float_as_int(e0.x));
        unsigned long long v0 = dup2(e0.y);
#pragma unroll
        for (int q = 0; q < 8; q++) {
            ulonglong2 w0 = r0[q];
            ffma2(agg[2*q],     v0, w0.x);
            ffma2(agg[2*q + 1], v0, w0.y);
        }
    }
    // bias + relu + store
    float h[HD];
#pragma unroll
    for (int p = 0; p < 16; p++) unpack2(h[2*p], h[2*p + 1], agg[p]);
    float4* row = (float4*)(bufD + t * ST);
#pragma unroll
    for (int q = 0; q < 8; q++) {
        float a0 = fmaxf(h[4*q]     + sbias[4*q],     0.f);
        float a1 = fmaxf(h[4*q + 1] + sbias[4*q + 1], 0.f);
        float a2 = fmaxf(h[4*q + 2] + sbias[4*q + 2], 0.f);
        float a3 = fmaxf(h[4*q + 3] + sbias[4*q + 3], 0.f);
        row[q] = make_float4(a0, a1, a2, a3);
    }
}

// ---------------------------------------------------------------------------
// Linear: thread = node, 32x32 matmul via packed fma.rn.f32x2.
// ---------------------------------------------------------------------------
__device__ __forceinline__ void linear_phase(const float* __restrict__ bufS,
                                             float* __restrict__ bufD,
                                             const float* __restrict__ W, int t)
{
    float h[HD];
    const float4* hr = (const float4*)(bufS + t * ST);
#pragma unroll
    for (int q = 0; q < 8; q++) {
        float4 v = hr[q];
        h[4*q] = v.x; h[4*q+1] = v.y; h[4*q+2] = v.z; h[4*q+3] = v.w;
    }
    unsigned long long y2[16];
#pragma unroll
    for (int q = 0; q < 16; q++) y2[q] = 0ULL;
#pragma unroll
    for (int k = 0; k < HD; k++) {
        unsigned long long hk = dup2(h[k]);
        const ulonglong2* Wr = (const ulonglong2*)(W + k * HD);
#pragma unroll
        for (int q = 0; q < 8; q++) {
            ulonglong2 wv = Wr[q];
            ffma2(y2[2*q],     hk, wv.x);
            ffma2(y2[2*q + 1], hk, wv.y);
        }
    }
    ulonglong2* out = (ulonglong2*)(bufD + t * ST);
#pragma unroll
    for (int q = 0; q < 8; q++) out[q] = make_ulonglong2(y2[2*q], y2[2*q+1]);
}

// ---------------------------------------------------------------------------
// Main GNN kernel: one CTA per batch element.
// ---------------------------------------------------------------------------
__global__ void __launch_bounds__(NN, 2) gnn_kernel(
    const float* __restrict__ gf, const float* __restrict__ vec,
    const float* __restrict__ W1, const float* __restrict__ b1,
    const float* __restrict__ W2, const float* __restrict__ b2,
    const float* __restrict__ W3, const float* __restrict__ b3,
    const float* __restrict__ We, const float* __restrict__ be)
{
    extern __shared__ float s[];
    float*  bufA = s;                          // 9216
    float*  bufB = bufA + NN * ST;             // 9216
    float2* sE   = (float2*)(bufB + NN * ST);  // 4608 floats
    int*    srow = (int*)(sE + EMAX);          // 260 (padded)
    float*  sW1  = (float*)(srow + 260);       // 192
    float*  sW2  = sW1 + 192;                  // 1024
    float*  sW3  = sW2 + 1024;                 // 1024
    float*  sWe  = sW3 + 1024;                 // 1024
    float*  sb   = sWe + 1024;                 // 128: b1|b2|b3|be

    int t = threadIdx.x;
    int b = blockIdx.x;

    // ---- stage CSR, weights, gf ----
    {
        const float4* ge4 = (const float4*)g_edge;
        float4* se4 = (float4*)sE;
        for (int i = t; i < EMAX / 2; i += NN) se4[i] = ge4[i];
        srow[t] = g_rowptr[t];
        if (t == 0) srow[NN] = g_rowptr[NN];
        if (t < FIN * HD) sW1[t] = W1[t];
        for (int i = t; i < HD * HD; i += NN) {
            sW2[i] = W2[i]; sW3[i] = W3[i]; sWe[i] = We[i];
        }
        if (t < HD) { sb[t] = b1[t]; sb[32+t] = b2[t]; sb[64+t] = b3[t]; sb[96+t] = be[t]; }
        const float4* g4 = (const float4*)(gf + (size_t)b * NN * FIN);
        float4* xb = (float4*)bufB;
        for (int i = t; i < NN * FIN / 4; i += NN) xb[i] = g4[i];
    }
    __syncthreads();

    // ---- phase 0: t0 = x @ W1 -> bufA ----
    {
        float x[FIN];
#pragma unroll
        for (int k = 0; k < FIN; k++) x[k] = bufB[t * FIN + k];
        unsigned long long y2[16];
#pragma unroll
        for (int q = 0; q < 16; q++) y2[q] = 0ULL;
#pragma unroll
        for (int k = 0; k < FIN; k++) {
            unsigned long long xk = dup2(x[k]);
            const ulonglong2* Wr = (const ulonglong2*)(sW1 + k * HD);
#pragma unroll
            for (int q = 0; q < 8; q++) {
                ulonglong2 wv = Wr[q];
                ffma2(y2[2*q], xk, wv.x);
                ffma2(y2[2*q+1], xk, wv.y);
            }
        }
        ulonglong2* row = (ulonglong2*)(bufA + t * ST);
#pragma unroll
        for (int q = 0; q < 8; q++) row[q] = make_ulonglong2(y2[2*q], y2[2*q+1]);
    }
    __syncthreads();

    gather2(bufA, bufB, sE, srow, sb, t);        // layer 1 agg+relu
    __syncthreads();
    linear_phase(bufB, bufA, sW2, t);            // h1 @ W2
    __syncthreads();
    gather2(bufA, bufB, sE, srow, sb + 32, t);   // layer 2 agg+relu
    __syncthreads();
    linear_phase(bufB, bufA, sW3, t);            // h2 @ W3
    __syncthreads();
    gather2(bufA, bufB, sE, srow, sb + 64, t);   // layer 3 agg+relu -> bufB
    __syncthreads();

    // ---- mean pool: tree reduction over rows of bufB ----
    for (int step = 128; step >= 1; step >>= 1) {
        if (t < step) {
            float4* a = (float4*)(bufB + t * ST);
            const float4* c = (const float4*)(bufB + (t + step) * ST);
#pragma unroll
            for (int q = 0; q < 8; q++) {
                float4 av = a[q], cv = c[q];
                a[q] = make_float4(av.x + cv.x, av.y + cv.y, av.z + cv.z, av.w + cv.w);
            }
        }
        __syncthreads();
    }

    // ---- embedding + comb write ----
    if (t < HD) {
        float e = sb[96 + t];
#pragma unroll
        for (int k = 0; k < HD; k++)
            e = fmaf(bufB[k] * (1.f / 256.f), sWe[k * HD + t], e);
        g_comb[b * 64 + VECD + t] = e;
    }
    if (t >= 64 && t < 64 + VECD)
        g_comb[b * 64 + (t - 64)] = vec[(size_t)b * VECD + (t - 64)];
}

// ---------------------------------------------------------------------------
// Heads: [1024 x 58] @ [58 x 512] x2; 128 CTAs x 8 batches so weights are
// read ~128x from L2 total instead of 1024x.
// ---------------------------------------------------------------------------
__global__ void __launch_bounds__(NN) heads_kernel(
    const float* __restrict__ Wpi, const float* __restrict__ bpi,
    const float* __restrict__ Wvf, const float* __restrict__ bvf,
    float* __restrict__ out)
{
    __shared__ float sc[8][64];
    int t = threadIdx.x;
    int b0 = blockIdx.x * 8;
    for (int i = t; i < 8 * 64; i += NN)
        sc[i >> 6][i & 63] = g_comb[(size_t)(b0 + (i >> 6)) * 64 + (i & 63)];
    __syncthreads();

    float a0[8], a1[8], a2[8], a3[8];
    float bp0 = bpi[t], bp1 = bpi[t + 256], bv0 = bvf[t], bv1 = bvf[t + 256];
#pragma unroll
    for (int i = 0; i < 8; i++) { a0[i] = bp0; a1[i] = bp1; a2[i] = bv0; a3[i] = bv1; }

#pragma unroll
    for (int k = 0; k < VECD + HD; k++) {
        float w0 = Wpi[k * DPI + t];
        float w1 = Wpi[k * DPI + t + 256];
        float w2 = Wvf[k * DPI + t];
        float w3 = Wvf[k * DPI + t + 256];
#pragma unroll
        for (int i = 0; i < 8; i++) {
            float c = sc[i][k];
            a0[i] = fmaf(w0, c, a0[i]);
            a1[i] = fmaf(w1, c, a1[i]);
            a2[i] = fmaf(w2, c, a2[i]);
            a3[i] = fmaf(w3, c, a3[i]);
        }
    }
#pragma unroll
    for (int i = 0; i < 8; i++) {
        size_t rb = (size_t)(b0 + i) * DPI;
        out[rb + t]                          = fmaxf(a0[i], 0.f);
        out[rb + t + 256]                    = fmaxf(a1[i], 0.f);
        out[(size_t)BB * DPI + rb + t]       = fmaxf(a2[i], 0.f);
        out[(size_t)BB * DPI + rb + t + 256] = fmaxf(a3[i], 0.f);
    }
}

extern "C" void kernel_launch(void* const* d_in, const int* in_sizes, int n_in,
                              void* d_out, int out_size) {
    const float* gf  = (const float*)d_in[0];
    const float* vec = (const float*)d_in[1];
    const int*   src = (const int*)d_in[2];
    const int*   dst = (const int*)d_in[3];
    const float* W1  = (const float*)d_in[4];
    const float* b1  = (const float*)d_in[5];
    const float* W2  = (const float*)d_in[6];
    const float* b2  = (const float*)d_in[7];
    const float* W3  = (const float*)d_in[8];
    const float* b3  = (const float*)d_in[9];
    const float* We  = (const float*)d_in[10];
    const float* be  = (const float*)d_in[11];
    const float* Wpi = (const float*)d_in[12];
    const float* bpi = (const float*)d_in[13];
    const float* Wvf = (const float*)d_in[14];
    const float* bvf = (const float*)d_in[15];

    int E = in_sizes[2];
    if (E > EMAX) E = EMAX;

    prep_kernel<<<1, NN>>>(src, dst, E);

    // smem floats: 2*9216 + 4608 + 260 + 192 + 3*1024 + 128 = 26692
    int smem = 26692 * (int)sizeof(float);
    cudaFuncSetAttribute(gnn_kernel, cudaFuncAttributeMaxDynamicSharedMemorySize, smem);
    gnn_kernel<<<BB, NN, smem>>>(gf, vec, W1, b1, W2, b2, W3, b3, We, be);
    heads_kernel<<<BB / 8, NN>>>(Wpi, bpi, Wvf, bvf, (float*)d_out);
}

// round 4
// speedup vs baseline: 1.4838x; 1.1650x over previous
#include <cuda_runtime.h>

#define NN    256
#define FIN   6
#define HD    32
#define VECD  26
#define DPI   512
#define BB    1024
#define EMAX  2304
#define EMAXP 2560   // even-padded capacity
#define ST    36     // padded row stride (floats): 16B-aligned rows

__device__ int g_degO[NN];            // zero-initialized; re-zeroed by prep2 each call
__device__ int g_degI[NN];
__device__ int g_rowptr[NN + 1];
__device__ __align__(16) float2 g_edge[EMAXP];  // .x = bits(col*ST), .y = norm
__device__ float g_comb[BB * 64];

// ---------------------------------------------------------------------------
// packed f32x2 helpers
// ---------------------------------------------------------------------------
__device__ __forceinline__ unsigned long long dup2(float v) {
    unsigned long long r;
    asm("mov.b64 %0, {%1, %1};" : "=l"(r) : "f"(v));
    return r;
}
__device__ __forceinline__ void ffma2(unsigned long long& a, unsigned long long x,
                                      unsigned long long y) {
    asm("fma.rn.f32x2 %0, %1, %2, %0;" : "+l"(a) : "l"(x), "l"(y));
}
__device__ __forceinline__ void unpack2(float& lo, float& hi, unsigned long long v) {
    asm("mov.b64 {%0, %1}, %2;" : "=f"(lo), "=f"(hi) : "l"(v));
}

// ---------------------------------------------------------------------------
// prep1: multi-CTA degree histogram via global red atomics (spread addresses).
// ---------------------------------------------------------------------------
__global__ void prep1_kernel(const int* __restrict__ src, const int* __restrict__ dst, int E) {
    int e = blockIdx.x * blockDim.x + threadIdx.x;
    if (e < E) {
        atomicAdd(&g_degO[src[e]], 1);
        atomicAdd(&g_degI[dst[e]], 1);
    }
}

// ---------------------------------------------------------------------------
// prep2: scan (even-padded), norms, scatter CSR, pad rows, re-zero degrees.
// ---------------------------------------------------------------------------
__global__ void prep2_kernel(const int* __restrict__ src, const int* __restrict__ dst, int E) {
    __shared__ float sO[NN], sI[NN];
    __shared__ int cur[NN];
    __shared__ int wsum[8];
    int t = threadIdx.x, lane = t & 31, w = t >> 5;
    int dO = g_degO[t], dI = g_degI[t];
    int dp = (dI + 1) & ~1;          // pad each row to even length
    int v = dp;
#pragma unroll
    for (int o = 1; o < 32; o <<= 1) {
        int nv_ = __shfl_up_sync(0xffffffffu, v, o);
        if (lane >= o) v += nv_;
    }
    if (lane == 31) wsum[w] = v;
    __syncthreads();
    if (t == 0) {
        int acc = 0;
#pragma unroll
        for (int i = 0; i < 8; i++) { acc += wsum[i]; wsum[i] = acc; }
    }
    __syncthreads();
    int excl = (w ? wsum[w - 1] : 0) + v - dp;
    g_rowptr[t] = excl;
    cur[t] = excl;
    if (t == NN - 1) g_rowptr[NN] = excl + dp;
    sO[t] = dO ? rsqrtf((float)dO) : 0.f;
    sI[t] = dI ? rsqrtf((float)dI) : 0.f;
    __syncthreads();
    for (int e = t; e < E; e += NN) {
        int s_ = src[e], d_ = dst[e];
        float nv = sO[s_] * sI[d_];
        int pos = atomicAdd(&cur[d_], 1);
        g_edge[pos] = make_float2(__int_as_float(s_ * ST), nv);
    }
    if (dI & 1) g_edge[excl + dI] = make_float2(__int_as_float(0), 0.f);  // zero pad edge
    g_degO[t] = 0;   // ready for next replay
    g_degI[t] = 0;
}

// ---------------------------------------------------------------------------
// Octet gather: 8 lanes per edge-row (lane q reads float4 q). Per instruction,
// 4 octets x 8 q cover all 8 bank-groups with exactly 4 lanes each ->
// exactly 4 crossbar phases regardless of row values. Even-degree rows ->
// sE pair loads are one aligned LDS.128, no tail.
// ---------------------------------------------------------------------------
__device__ __forceinline__ void gatherO(const float* __restrict__ bufS,
                                        float* __restrict__ bufD,
                                        const float2* __restrict__ sE,
                                        const int* __restrict__ srow,
                                        const float* __restrict__ sbias, int t)
{
    int l = t & 31, w = t >> 5;
    int o = l >> 3, q = l & 7;
    const float* bufq = bufS + 4 * q;
    float4 bv = *(const float4*)(sbias + 4 * q);
#pragma unroll
    for (int p = 0; p < 8; p++) {
        int n = p * 32 + w * 4 + o;
        int rs = srow[n], re = srow[n + 1];
        unsigned long long a0 = 0, a1 = 0, a2 = 0, a3 = 0;
        for (int j = rs; j < re; j += 2) {
            float4 ep = *(const float4*)((const float*)sE + 2 * j);
            ulonglong2 x0 = *(const ulonglong2*)(bufq + __float_as_int(ep.x));
            ulonglong2 x1 = *(const ulonglong2*)(bufq + __float_as_int(ep.z));
            unsigned long long v0 = dup2(ep.y), v1 = dup2(ep.w);
            ffma2(a0, v0, x0.x); ffma2(a1, v0, x0.y);
            ffma2(a2, v1, x1.x); ffma2(a3, v1, x1.y);
        }
        float r0, r1, r2, r3, s0, s1, s2, s3;
        unpack2(r0, r1, a0); unpack2(r2, r3, a1);
        unpack2(s0, s1, a2); unpack2(s2, s3, a3);
        float4 hv;
        hv.x = fmaxf(r0 + s0 + bv.x, 0.f);
        hv.y = fmaxf(r1 + s1 + bv.y, 0.f);
        hv.z = fmaxf(r2 + s2 + bv.z, 0.f);
        hv.w = fmaxf(r3 + s3 + bv.w, 0.f);
        *(float4*)(bufD + n * ST + 4 * q) = hv;
    }
}

// ---------------------------------------------------------------------------
// Linear: thread = node, 32x32 via packed fma.rn.f32x2. Consecutive rows ->
// conflict-free h loads/stores; W loads are warp-uniform broadcasts.
// ---------------------------------------------------------------------------
__device__ __forceinline__ void linear_phase(const float* __restrict__ bufS,
                                             float* __restrict__ bufD,
                                             const float* __restrict__ W, int t)
{
    float h[HD];
    const float4* hr = (const float4*)(bufS + t * ST);
#pragma unroll
    for (int q = 0; q < 8; q++) {
        float4 v = hr[q];
        h[4*q] = v.x; h[4*q+1] = v.y; h[4*q+2] = v.z; h[4*q+3] = v.w;
    }
    unsigned long long y2[16];
#pragma unroll
    for (int q = 0; q < 16; q++) y2[q] = 0ULL;
#pragma unroll
    for (int k = 0; k < HD; k++) {
        unsigned long long hk = dup2(h[k]);
        const ulonglong2* Wr = (const ulonglong2*)(W + k * HD);
#pragma unroll
        for (int q = 0; q < 8; q++) {
            ulonglong2 wv = Wr[q];
            ffma2(y2[2*q],     hk, wv.x);
            ffma2(y2[2*q + 1], hk, wv.y);
        }
    }
    ulonglong2* out = (ulonglong2*)(bufD + t * ST);
#pragma unroll
    for (int q = 0; q < 8; q++) out[q] = make_ulonglong2(y2[2*q], y2[2*q+1]);
}

// ---------------------------------------------------------------------------
// Main GNN kernel: one CTA per batch element.
// ---------------------------------------------------------------------------
__global__ void __launch_bounds__(NN, 2) gnn_kernel(
    const float* __restrict__ gf, const float* __restrict__ vec,
    const float* __restrict__ W1, const float* __restrict__ b1,
    const float* __restrict__ W2, const float* __restrict__ b2,
    const float* __restrict__ W3, const float* __restrict__ b3,
    const float* __restrict__ We, const float* __restrict__ be)
{
    extern __shared__ float s[];
    float*  bufA = s;                          // 9216
    float*  bufB = bufA + NN * ST;             // 9216
    float2* sE   = (float2*)(bufB + NN * ST);  // 2*2560 floats
    int*    srow = (int*)(sE + EMAXP);         // 260 (padded)
    float*  sW1  = (float*)(srow + 260);       // 192
    float*  sW2  = sW1 + 192;                  // 1024
    float*  sW3  = sW2 + 1024;                 // 1024
    float*  sWe  = sW3 + 1024;                 // 1024
    float*  sb   = sWe + 1024;                 // 128: b1|b2|b3|be

    int t = threadIdx.x;
    int b = blockIdx.x;

    // ---- stage CSR, weights, gf ----
    {
        const float4* ge4 = (const float4*)g_edge;
        float4* se4 = (float4*)sE;
#pragma unroll
        for (int i = 0; i < EMAXP / 2 / NN; i++) se4[t + i * NN] = ge4[t + i * NN];
        srow[t] = g_rowptr[t];
        if (t == 0) srow[NN] = g_rowptr[NN];
        if (t < FIN * HD) sW1[t] = W1[t];
        for (int i = t; i < HD * HD; i += NN) {
            sW2[i] = W2[i]; sW3[i] = W3[i]; sWe[i] = We[i];
        }
        if (t < HD) { sb[t] = b1[t]; sb[32+t] = b2[t]; sb[64+t] = b3[t]; sb[96+t] = be[t]; }
        const float4* g4 = (const float4*)(gf + (size_t)b * NN * FIN);
        float4* xb = (float4*)bufB;
#pragma unroll
        for (int i = 0; i < NN * FIN / 4 / NN; i++) xb[t + i * NN] = g4[t + i * NN];
    }
    __syncthreads();

    // ---- phase 0: t0 = x @ W1 -> bufA ----
    {
        float x[FIN];
#pragma unroll
        for (int k = 0; k < FIN; k++) x[k] = bufB[t * FIN + k];
        unsigned long long y2[16];
#pragma unroll
        for (int q = 0; q < 16; q++) y2[q] = 0ULL;
#pragma unroll
        for (int k = 0; k < FIN; k++) {
            unsigned long long xk = dup2(x[k]);
            const ulonglong2* Wr = (const ulonglong2*)(sW1 + k * HD);
#pragma unroll
            for (int q = 0; q < 8; q++) {
                ulonglong2 wv = Wr[q];
                ffma2(y2[2*q], xk, wv.x);
                ffma2(y2[2*q+1], xk, wv.y);
            }
        }
        ulonglong2* row = (ulonglong2*)(bufA + t * ST);
#pragma unroll
        for (int q = 0; q < 8; q++) row[q] = make_ulonglong2(y2[2*q], y2[2*q+1]);
    }
    __syncthreads();

    gatherO(bufA, bufB, sE, srow, sb, t);        // layer 1 agg+relu
    __syncthreads();
    linear_phase(bufB, bufA, sW2, t);            // h1 @ W2
    __syncthreads();
    gatherO(bufA, bufB, sE, srow, sb + 32, t);   // layer 2 agg+relu
    __syncthreads();
    linear_phase(bufB, bufA, sW3, t);            // h2 @ W3
    __syncthreads();
    gatherO(bufA, bufB, sE, srow, sb + 64, t);   // layer 3 agg+relu -> bufB
    __syncthreads();

    // ---- mean pool: tree reduction over rows of bufB ----
    for (int step = 128; step >= 1; step >>= 1) {
        if (t < step) {
            float4* a = (float4*)(bufB + t * ST);
            const float4* c = (const float4*)(bufB + (t + step) * ST);
#pragma unroll
            for (int q = 0; q < 8; q++) {
                float4 av = a[q], cv = c[q];
                a[q] = make_float4(av.x + cv.x, av.y + cv.y, av.z + cv.z, av.w + cv.w);
            }
        }
        __syncthreads();
    }

    // ---- embedding + comb write ----
    if (t < HD) {
        float e = sb[96 + t];
#pragma unroll
        for (int k = 0; k < HD; k++)
            e = fmaf(bufB[k] * (1.f / 256.f), sWe[k * HD + t], e);
        g_comb[b * 64 + VECD + t] = e;
    }
    if (t >= 64 && t < 64 + VECD)
        g_comb[b * 64 + (t - 64)] = vec[(size_t)b * VECD + (t - 64)];
}

// ---------------------------------------------------------------------------
// Heads: [1024 x 58] @ [58 x 512] x2; 128 CTAs x 8 batches.
// ---------------------------------------------------------------------------
__global__ void __launch_bounds__(NN) heads_kernel(
    const float* __restrict__ Wpi, const float* __restrict__ bpi,
    const float* __restrict__ Wvf, const float* __restrict__ bvf,
    float* __restrict__ out)
{
    __shared__ float sc[8][64];
    int t = threadIdx.x;
    int b0 = blockIdx.x * 8;
    for (int i = t; i < 8 * 64; i += NN)
        sc[i >> 6][i & 63] = g_comb[(size_t)(b0 + (i >> 6)) * 64 + (i & 63)];
    __syncthreads();

    float a0[8], a1[8], a2[8], a3[8];
    float bp0 = bpi[t], bp1 = bpi[t + 256], bv0 = bvf[t], bv1 = bvf[t + 256];
#pragma unroll
    for (int i = 0; i < 8; i++) { a0[i] = bp0; a1[i] = bp1; a2[i] = bv0; a3[i] = bv1; }

#pragma unroll
    for (int k = 0; k < VECD + HD; k++) {
        float w0 = Wpi[k * DPI + t];
        float w1 = Wpi[k * DPI + t + 256];
        float w2 = Wvf[k * DPI + t];
        float w3 = Wvf[k * DPI + t + 256];
#pragma unroll
        for (int i = 0; i < 8; i++) {
            float c = sc[i][k];
            a0[i] = fmaf(w0, c, a0[i]);
            a1[i] = fmaf(w1, c, a1[i]);
            a2[i] = fmaf(w2, c, a2[i]);
            a3[i] = fmaf(w3, c, a3[i]);
        }
    }
#pragma unroll
    for (int i = 0; i < 8; i++) {
        size_t rb = (size_t)(b0 + i) * DPI;
        out[rb + t]                          = fmaxf(a0[i], 0.f);
        out[rb + t + 256]                    = fmaxf(a1[i], 0.f);
        out[(size_t)BB * DPI + rb + t]       = fmaxf(a2[i], 0.f);
        out[(size_t)BB * DPI + rb + t + 256] = fmaxf(a3[i], 0.f);
    }
}

extern "C" void kernel_launch(void* const* d_in, const int* in_sizes, int n_in,
                              void* d_out, int out_size) {
    const float* gf  = (const float*)d_in[0];
    const float* vec = (const float*)d_in[1];
    const int*   src = (const int*)d_in[2];
    const int*   dst = (const int*)d_in[3];
    const float* W1  = (const float*)d_in[4];
    const float* b1  = (const float*)d_in[5];
    const float* W2  = (const float*)d_in[6];
    const float* b2  = (const float*)d_in[7];
    const float* W3  = (const float*)d_in[8];
    const float* b3  = (const float*)d_in[9];
    const float* We  = (const float*)d_in[10];
    const float* be  = (const float*)d_in[11];
    const float* Wpi = (const float*)d_in[12];
    const float* bpi = (const float*)d_in[13];
    const float* Wvf = (const float*)d_in[14];
    const float* bvf = (const float*)d_in[15];

    int E = in_sizes[2];
    if (E > EMAX) E = EMAX;

    prep1_kernel<<<(E + NN - 1) / NN, NN>>>(src, dst, E);
    prep2_kernel<<<1, NN>>>(src, dst, E);

    // smem floats: 2*9216 + 5120 + 260 + 192 + 3*1024 + 128 = 27204
    int smem = 27204 * (int)sizeof(float);
    cudaFuncSetAttribute(gnn_kernel, cudaFuncAttributeMaxDynamicSharedMemorySize, smem);
    gnn_kernel<<<BB, NN, smem>>>(gf, vec, W1, b1, W2, b2, W3, b3, We, be);
    heads_kernel<<<BB / 8, NN>>>(Wpi, bpi, Wvf, bvf, (float*)d_out);
}

// round 5
// speedup vs baseline: 1.7719x; 1.1942x over previous
#include <cuda_runtime.h>

#define NN    256
#define FIN   6
#define HD    32
#define VECD  26
#define DPI   512
#define BB    1024
#define EMAX  2304
#define EMAXP 2568   // even-padded capacity + zero slots
#define PADJ  2564   // even pair index pointing at guaranteed-zero edges
#define ST    36     // padded row stride (floats)

__device__ int g_degO[NN];
__device__ int g_degI[NN];
__device__ int g_rowptr[NN + 1];
__device__ __align__(16) float2 g_edge[EMAXP];
__device__ float g_comb[BB * 64];

// ---------------------------------------------------------------------------
// packed f32x2 helpers
// ---------------------------------------------------------------------------
__device__ __forceinline__ unsigned long long dup2(float v) {
    unsigned long long r;
    asm("mov.b64 %0, {%1, %1};" : "=l"(r) : "f"(v));
    return r;
}
__device__ __forceinline__ unsigned long long pack2(float lo, float hi) {
    unsigned long long r;
    asm("mov.b64 %0, {%1, %2};" : "=l"(r) : "f"(lo), "f"(hi));
    return r;
}
__device__ __forceinline__ void ffma2(unsigned long long& a, unsigned long long x,
                                      unsigned long long y) {
    asm("fma.rn.f32x2 %0, %1, %2, %0;" : "+l"(a) : "l"(x), "l"(y));
}
__device__ __forceinline__ void unpack2(float& lo, float& hi, unsigned long long v) {
    asm("mov.b64 {%0, %1}, %2;" : "=f"(lo), "=f"(hi) : "l"(v));
}

// ---------------------------------------------------------------------------
// prep1: multi-CTA degree histogram (spread global atomics).
// ---------------------------------------------------------------------------
__global__ void prep1_kernel(const int* __restrict__ src, const int* __restrict__ dst, int E) {
    int e = blockIdx.x * blockDim.x + threadIdx.x;
    if (e < E) {
        atomicAdd(&g_degO[src[e]], 1);
        atomicAdd(&g_degI[dst[e]], 1);
    }
}

// ---------------------------------------------------------------------------
// prep2: scan (even-padded), norms, scatter CSR, zero pads, re-zero degrees.
// ---------------------------------------------------------------------------
__global__ void prep2_kernel(const int* __restrict__ src, const int* __restrict__ dst, int E) {
    __shared__ float sO[NN], sI[NN];
    __shared__ int cur[NN];
    __shared__ int wsum[8];
    int t = threadIdx.x, lane = t & 31, w = t >> 5;
    int dO = g_degO[t], dI = g_degI[t];
    int dp = (dI + 1) & ~1;
    int v = dp;
#pragma unroll
    for (int o = 1; o < 32; o <<= 1) {
        int nv_ = __shfl_up_sync(0xffffffffu, v, o);
        if (lane >= o) v += nv_;
    }
    if (lane == 31) wsum[w] = v;
    __syncthreads();
    if (t == 0) {
        int acc = 0;
#pragma unroll
        for (int i = 0; i < 8; i++) { acc += wsum[i]; wsum[i] = acc; }
    }
    __syncthreads();
    int excl = (w ? wsum[w - 1] : 0) + v - dp;
    g_rowptr[t] = excl;
    cur[t] = excl;
    if (t == NN - 1) g_rowptr[NN] = excl + dp;
    sO[t] = dO ? rsqrtf((float)dO) : 0.f;
    sI[t] = dI ? rsqrtf((float)dI) : 0.f;
    __syncthreads();
    for (int e = t; e < E; e += NN) {
        int s_ = src[e], d_ = dst[e];
        float nv = sO[s_] * sI[d_];
        int pos = atomicAdd(&cur[d_], 1);
        g_edge[pos] = make_float2(__int_as_float(s_ * ST), nv);
    }
    if (dI & 1) g_edge[excl + dI] = make_float2(__int_as_float(0), 0.f);
    if (t < 8) g_edge[2560 + t] = make_float2(__int_as_float(0), 0.f);  // PADJ zeros
    g_degO[t] = 0;
    g_degI[t] = 0;
}

// ---------------------------------------------------------------------------
// Octet gather, dual-node interleaved (n and n+128), branchless tail via PADJ.
// POOL=1: no stores; mean-pool partials reduced via shfl.bfly.
// ---------------------------------------------------------------------------
template <int POOL>
__device__ __forceinline__ void gatherO(const float* __restrict__ bufS,
                                        float* __restrict__ bufD,
                                        const float* __restrict__ sEf,
                                        const int* __restrict__ srow,
                                        const float* __restrict__ sbias,
                                        float* __restrict__ pool, int t)
{
    int l = t & 31, w = t >> 5;
    int o = l >> 3, q = l & 7;
    const float* bufq = bufS + 4 * q;
    float4 bv = *(const float4*)(sbias + 4 * q);
    float4 ps = make_float4(0.f, 0.f, 0.f, 0.f);
#pragma unroll
    for (int pp = 0; pp < 4; pp++) {
        int nA = pp * 32 + w * 4 + o;
        int nB = nA + 128;
        int jA = srow[nA], eA = srow[nA + 1];
        int jB = srow[nB], eB = srow[nB + 1];
        unsigned long long a0 = 0, a1 = 0, a2 = 0, a3 = 0;
        unsigned long long c0 = 0, c1 = 0, c2 = 0, c3 = 0;
        while (jA < eA || jB < eB) {
            int iA = jA < eA ? jA : PADJ;
            int iB = jB < eB ? jB : PADJ;
            float4 eA4 = *(const float4*)(sEf + 2 * iA);
            float4 eB4 = *(const float4*)(sEf + 2 * iB);
            ulonglong2 xA0 = *(const ulonglong2*)(bufq + __float_as_int(eA4.x));
            ulonglong2 xA1 = *(const ulonglong2*)(bufq + __float_as_int(eA4.z));
            ulonglong2 xB0 = *(const ulonglong2*)(bufq + __float_as_int(eB4.x));
            ulonglong2 xB1 = *(const ulonglong2*)(bufq + __float_as_int(eB4.z));
            unsigned long long vA0 = dup2(eA4.y), vA1 = dup2(eA4.w);
            unsigned long long vB0 = dup2(eB4.y), vB1 = dup2(eB4.w);
            ffma2(a0, vA0, xA0.x); ffma2(a1, vA0, xA0.y);
            ffma2(a2, vA1, xA1.x); ffma2(a3, vA1, xA1.y);
            ffma2(c0, vB0, xB0.x); ffma2(c1, vB0, xB0.y);
            ffma2(c2, vB1, xB1.x); ffma2(c3, vB1, xB1.y);
            jA += 2; jB += 2;
        }
        float r0, r1, r2, r3, s0, s1, s2, s3;
        unpack2(r0, r1, a0); unpack2(r2, r3, a1);
        unpack2(s0, s1, a2); unpack2(s2, s3, a3);
        float4 hA;
        hA.x = fmaxf(r0 + s0 + bv.x, 0.f);
        hA.y = fmaxf(r1 + s1 + bv.y, 0.f);
        hA.z = fmaxf(r2 + s2 + bv.z, 0.f);
        hA.w = fmaxf(r3 + s3 + bv.w, 0.f);
        unpack2(r0, r1, c0); unpack2(r2, r3, c1);
        unpack2(s0, s1, c2); unpack2(s2, s3, c3);
        float4 hB;
        hB.x = fmaxf(r0 + s0 + bv.x, 0.f);
        hB.y = fmaxf(r1 + s1 + bv.y, 0.f);
        hB.z = fmaxf(r2 + s2 + bv.z, 0.f);
        hB.w = fmaxf(r3 + s3 + bv.w, 0.f);
        if (POOL) {
            ps.x += hA.x + hB.x; ps.y += hA.y + hB.y;
            ps.z += hA.z + hB.z; ps.w += hA.w + hB.w;
        } else {
            *(float4*)(bufD + nA * ST + 4 * q) = hA;
            *(float4*)(bufD + nB * ST + 4 * q) = hB;
        }
    }
    if (POOL) {
#pragma unroll
        for (int m = 8; m <= 16; m <<= 1) {
            ps.x += __shfl_xor_sync(0xffffffffu, ps.x, m);
            ps.y += __shfl_xor_sync(0xffffffffu, ps.y, m);
            ps.z += __shfl_xor_sync(0xffffffffu, ps.z, m);
            ps.w += __shfl_xor_sync(0xffffffffu, ps.w, m);
        }
        if (l < 8) *(float4*)(pool + (w * 8 + q) * 4) = ps;
    }
}

// ---------------------------------------------------------------------------
// Linear: thread = node, 32x32 via packed fma.rn.f32x2.
// ---------------------------------------------------------------------------
__device__ __forceinline__ void linear_phase(const float* __restrict__ bufS,
                                             float* __restrict__ bufD,
                                             const float* __restrict__ W, int t)
{
    float h[HD];
    const float4* hr = (const float4*)(bufS + t * ST);
#pragma unroll
    for (int q = 0; q < 8; q++) {
        float4 v = hr[q];
        h[4*q] = v.x; h[4*q+1] = v.y; h[4*q+2] = v.z; h[4*q+3] = v.w;
    }
    unsigned long long y2[16];
#pragma unroll
    for (int q = 0; q < 16; q++) y2[q] = 0ULL;
#pragma unroll
    for (int k = 0; k < HD; k++) {
        unsigned long long hk = dup2(h[k]);
        const ulonglong2* Wr = (const ulonglong2*)(W + k * HD);
#pragma unroll
        for (int q = 0; q < 8; q++) {
            ulonglong2 wv = Wr[q];
            ffma2(y2[2*q],     hk, wv.x);
            ffma2(y2[2*q + 1], hk, wv.y);
        }
    }
    ulonglong2* out = (ulonglong2*)(bufD + t * ST);
#pragma unroll
    for (int q = 0; q < 8; q++) out[q] = make_ulonglong2(y2[2*q], y2[2*q+1]);
}

// ---------------------------------------------------------------------------
// Main GNN kernel: one CTA per batch element.
// ---------------------------------------------------------------------------
__global__ void __launch_bounds__(NN, 2) gnn_kernel(
    const float* __restrict__ gf, const float* __restrict__ vec,
    const float* __restrict__ W1, const float* __restrict__ b1,
    const float* __restrict__ W2, const float* __restrict__ b2,
    const float* __restrict__ W3, const float* __restrict__ b3,
    const float* __restrict__ We, const float* __restrict__ be)
{
    extern __shared__ float s[];
    float* bufA = s;                         // 9216
    float* bufB = bufA + NN * ST;            // 9216
    float* sEf  = bufB + NN * ST;            // 2*EMAXP = 5136
    int*   srow = (int*)(sEf + 2 * EMAXP);   // 260
    float* sW1  = (float*)(srow + 260);      // 192
    float* sW2  = sW1 + 192;                 // 1024
    float* sW3  = sW2 + 1024;                // 1024
    float* sWe  = sW3 + 1024;                // 1024
    float* sb   = sWe + 1024;                // 128
    float* pool = sb + 128;                  // 256
    float* hg   = pool + 256;                // 32

    int t = threadIdx.x;
    int b = blockIdx.x;

    // ---- stage CSR, weights, gf ----
    {
        const float4* ge4 = (const float4*)g_edge;
        float4* se4 = (float4*)sEf;
        for (int i = t; i < EMAXP / 2; i += NN) se4[i] = ge4[i];
        srow[t] = g_rowptr[t];
        if (t == 0) srow[NN] = g_rowptr[NN];
        if (t < FIN * HD) sW1[t] = W1[t];
        for (int i = t; i < HD * HD; i += NN) {
            sW2[i] = W2[i]; sW3[i] = W3[i]; sWe[i] = We[i];
        }
        if (t < HD) { sb[t] = b1[t]; sb[32+t] = b2[t]; sb[64+t] = b3[t]; sb[96+t] = be[t]; }
        const float4* g4 = (const float4*)(gf + (size_t)b * NN * FIN);
        float4* xb = (float4*)bufB;
#pragma unroll
        for (int i = 0; i < NN * FIN / 4 / NN; i++) xb[t + i * NN] = g4[t + i * NN];
    }
    __syncthreads();

    // ---- phase 0: t0 = x @ W1 -> bufA ----
    {
        float x[FIN];
#pragma unroll
        for (int k = 0; k < FIN; k++) x[k] = bufB[t * FIN + k];
        unsigned long long y2[16];
#pragma unroll
        for (int q = 0; q < 16; q++) y2[q] = 0ULL;
#pragma unroll
        for (int k = 0; k < FIN; k++) {
            unsigned long long xk = dup2(x[k]);
            const ulonglong2* Wr = (const ulonglong2*)(sW1 + k * HD);
#pragma unroll
            for (int q = 0; q < 8; q++) {
                ulonglong2 wv = Wr[q];
                ffma2(y2[2*q], xk, wv.x);
                ffma2(y2[2*q+1], xk, wv.y);
            }
        }
        ulonglong2* row = (ulonglong2*)(bufA + t * ST);
#pragma unroll
        for (int q = 0; q < 8; q++) row[q] = make_ulonglong2(y2[2*q], y2[2*q+1]);
    }
    __syncthreads();

    gatherO<0>(bufA, bufB, sEf, srow, sb, pool, t);        // layer 1
    __syncthreads();
    linear_phase(bufB, bufA, sW2, t);                      // h1 @ W2
    __syncthreads();
    gatherO<0>(bufA, bufB, sEf, srow, sb + 32, pool, t);   // layer 2
    __syncthreads();
    linear_phase(bufB, bufA, sW3, t);                      // h2 @ W3
    __syncthreads();
    gatherO<1>(bufA, bufB, sEf, srow, sb + 64, pool, t);   // layer 3 + pool partials
    __syncthreads();

    // ---- finish mean pool: 8 warps' partials per quad ----
    if (t < 8) {
        float4 sum = make_float4(0.f, 0.f, 0.f, 0.f);
#pragma unroll
        for (int w = 0; w < 8; w++) {
            float4 v = *(const float4*)(pool + (w * 8 + t) * 4);
            sum.x += v.x; sum.y += v.y; sum.z += v.z; sum.w += v.w;
        }
        const float inv = 1.f / 256.f;
        hg[4*t]   = sum.x * inv; hg[4*t+1] = sum.y * inv;
        hg[4*t+2] = sum.z * inv; hg[4*t+3] = sum.w * inv;
    }
    __syncthreads();

    // ---- embedding + comb write ----
    if (t < HD) {
        float e = sb[96 + t];
#pragma unroll
        for (int k = 0; k < HD; k++)
            e = fmaf(hg[k], sWe[k * HD + t], e);
        g_comb[b * 64 + VECD + t] = e;
    }
    if (t >= 64 && t < 64 + VECD)
        g_comb[b * 64 + (t - 64)] = vec[(size_t)b * VECD + (t - 64)];
}

// ---------------------------------------------------------------------------
// Heads: smem-tiled GEMM. grid = 16 batch-tiles(64) x 8 col-tiles(128).
// Thread: 4 batches x 4 col-pairs in packed f32x2 accumulators.
// ---------------------------------------------------------------------------
__global__ void __launch_bounds__(NN) heads_kernel(
    const float* __restrict__ Wpi, const float* __restrict__ bpi,
    const float* __restrict__ Wvf, const float* __restrict__ bvf,
    float* __restrict__ out)
{
    __shared__ float sW[58 * 128];
    __shared__ unsigned long long sC[64 * 58];
    __shared__ float sbias[128];

    int t = threadIdx.x;
    int btile = blockIdx.x & 15;
    int ctile = blockIdx.x >> 4;
    int head = ctile >> 2;
    int colbase = (ctile & 3) * 128;
    const float* W = head ? Wvf : Wpi;
    const float* bias = head ? bvf : bpi;

    // stage W slice [58][128]
    for (int i = t; i < 58 * 32; i += NN) {
        int k = i >> 5, c4 = i & 31;
        *(float4*)(sW + k * 128 + c4 * 4) =
            *(const float4*)(W + k * DPI + colbase + c4 * 4);
    }
    if (t < 128) sbias[t] = bias[colbase + t];
    // stage comb tile, duplicated to packed pairs
    for (int i = t; i < 64 * 58; i += NN) {
        int bb = i / 58, k = i - bb * 58;
        sC[i] = dup2(g_comb[(size_t)(btile * 64 + bb) * 64 + k]);
    }
    __syncthreads();

    int pg = t & 15, bg = t >> 4;
    const unsigned long long* Cb = sC + (bg * 4) * 58;

    unsigned long long acc[4][4];
#pragma unroll
    for (int ss = 0; ss < 4; ss++) {
        int cp = (pg + ss * 16) * 2;
        unsigned long long bp = pack2(sbias[cp], sbias[cp + 1]);
#pragma unroll
        for (int i = 0; i < 4; i++) acc[i][ss] = bp;
    }

#pragma unroll 2
    for (int k = 0; k < 58; k++) {
        unsigned long long wv[4];
#pragma unroll
        for (int ss = 0; ss < 4; ss++)
            wv[ss] = *(const unsigned long long*)(sW + k * 128 + (pg + ss * 16) * 2);
#pragma unroll
        for (int i = 0; i < 4; i++) {
            unsigned long long c = Cb[i * 58 + k];
#pragma unroll
            for (int ss = 0; ss < 4; ss++) ffma2(acc[i][ss], c, wv[ss]);
        }
    }

#pragma unroll
    for (int i = 0; i < 4; i++) {
        int bb = btile * 64 + bg * 4 + i;
        size_t rb = (size_t)head * BB * DPI + (size_t)bb * DPI + colbase;
#pragma unroll
        for (int ss = 0; ss < 4; ss++) {
            float lo, hi;
            unpack2(lo, hi, acc[i][ss]);
            int col = (pg + ss * 16) * 2;
            *(float2*)(out + rb + col) = make_float2(fmaxf(lo, 0.f), fmaxf(hi, 0.f));
        }
    }
}

extern "C" void kernel_launch(void* const* d_in, const int* in_sizes, int n_in,
                              void* d_out, int out_size) {
    const float* gf  = (const float*)d_in[0];
    const float* vec = (const float*)d_in[1];
    const int*   src = (const int*)d_in[2];
    const int*   dst = (const int*)d_in[3];
    const float* W1  = (const float*)d_in[4];
    const float* b1  = (const float*)d_in[5];
    const float* W2  = (const float*)d_in[6];
    const float* b2  = (const float*)d_in[7];
    const float* W3  = (const float*)d_in[8];
    const float* b3  = (const float*)d_in[9];
    const float* We  = (const float*)d_in[10];
    const float* be  = (const float*)d_in[11];
    const float* Wpi = (const float*)d_in[12];
    const float* bpi = (const float*)d_in[13];
    const float* Wvf = (const float*)d_in[14];
    const float* bvf = (const float*)d_in[15];

    int E = in_sizes[2];
    if (E > EMAX) E = EMAX;

    prep1_kernel<<<(E + NN - 1) / NN, NN>>>(src, dst, E);
    prep2_kernel<<<1, NN>>>(src, dst, E);

    // smem floats: 2*9216 + 5136 + 260 + 192 + 3*1024 + 128 + 256 + 32 = 27508
    int smem = 27508 * (int)sizeof(float);
    cudaFuncSetAttribute(gnn_kernel, cudaFuncAttributeMaxDynamicSharedMemorySize, smem);
    gnn_kernel<<<BB, NN, smem>>>(gf, vec, W1, b1, W2, b2, W3, b3, We, be);
    heads_kernel<<<128, NN>>>(Wpi, bpi, Wvf, bvf, (float*)d_out);
}

// round 8
// speedup vs baseline: 1.9533x; 1.1024x over previous
#include <cuda_runtime.h>

#define NN    256
#define FIN   6
#define HD    32
#define VECD  26
#define DPI   512
#define BB    1024
#define EMAX  2304
#define EMAXP 2568   // even-padded capacity + zero slots
#define PADJ  2564   // even pair index at guaranteed-zero edges
#define ST    36     // padded row stride (floats)

__device__ int g_degO[NN];
__device__ int g_degI[NN];
__device__ int g_rowptr[NN + 1];
__device__ int g_perm[NN];
__device__ __align__(16) float2 g_edge[EMAXP];
__device__ float g_comb[BB * 64];

// ---------------------------------------------------------------------------
// packed f32x2 helpers
// ---------------------------------------------------------------------------
__device__ __forceinline__ unsigned long long dup2(float v) {
    unsigned long long r;
    asm("mov.b64 %0, {%1, %1};" : "=l"(r) : "f"(v));
    return r;
}
__device__ __forceinline__ unsigned long long pack2(float lo, float hi) {
    unsigned long long r;
    asm("mov.b64 %0, {%1, %2};" : "=l"(r) : "f"(lo), "f"(hi));
    return r;
}
__device__ __forceinline__ void ffma2(unsigned long long& a, unsigned long long x,
                                      unsigned long long y) {
    asm("fma.rn.f32x2 %0, %1, %2, %0;" : "+l"(a) : "l"(x), "l"(y));
}
__device__ __forceinline__ void unpack2(float& lo, float& hi, unsigned long long v) {
    asm("mov.b64 {%0, %1}, %2;" : "=f"(lo), "=f"(hi) : "l"(v));
}

// ---------------------------------------------------------------------------
// prep1: multi-CTA degree histogram (spread global atomics).
// ---------------------------------------------------------------------------
__global__ void prep1_kernel(const int* __restrict__ src, const int* __restrict__ dst, int E) {
    int e = blockIdx.x * blockDim.x + threadIdx.x;
    if (e < E) {
        atomicAdd(&g_degO[src[e]], 1);
        atomicAdd(&g_degI[dst[e]], 1);
    }
}

// ---------------------------------------------------------------------------
// prep2: scan, norms, scatter CSR, counting-sort nodes by padded degree.
// ---------------------------------------------------------------------------
__global__ void prep2_kernel(const int* __restrict__ src, const int* __restrict__ dst, int E) {
    __shared__ float sO[NN], sI[NN];
    __shared__ int cur[NN];
    __shared__ int wsum[8];
    __shared__ int cnt[128];
    int t = threadIdx.x, lane = t & 31, w = t >> 5;
    int dO = g_degO[t], dI = g_degI[t];
    int dp = (dI + 1) & ~1;
    if (t < 128) cnt[t] = 0;
    int v = dp;
#pragma unroll
    for (int o = 1; o < 32; o <<= 1) {
        int nv_ = __shfl_up_sync(0xffffffffu, v, o);
        if (lane >= o) v += nv_;
    }
    if (lane == 31) wsum[w] = v;
    __syncthreads();
    if (t == 0) {
        int acc = 0;
#pragma unroll
        for (int i = 0; i < 8; i++) { acc += wsum[i]; wsum[i] = acc; }
    }
    int bin = dp >> 1; if (bin > 127) bin = 127;
    atomicAdd(&cnt[bin], 1);
    __syncthreads();
    int excl = (w ? wsum[w - 1] : 0) + v - dp;
    g_rowptr[t] = excl;
    cur[t] = excl;
    if (t == NN - 1) g_rowptr[NN] = excl + dp;
    sO[t] = dO ? rsqrtf((float)dO) : 0.f;
    sI[t] = dI ? rsqrtf((float)dI) : 0.f;
    // exclusive scan over 128 bins (warp 0, 4 bins/lane)
    if (t < 32) {
        int c0 = cnt[t*4], c1 = cnt[t*4+1], c2 = cnt[t*4+2], c3 = cnt[t*4+3];
        int tot = c0 + c1 + c2 + c3;
        int sc = tot;
#pragma unroll
        for (int o = 1; o < 32; o <<= 1) {
            int nv_ = __shfl_up_sync(0xffffffffu, sc, o);
            if (lane >= o) sc += nv_;
        }
        int base = sc - tot;
        cnt[t*4]   = base;
        cnt[t*4+1] = base + c0;
        cnt[t*4+2] = base + c0 + c1;
        cnt[t*4+3] = base + c0 + c1 + c2;
    }
    __syncthreads();
    int pos = atomicAdd(&cnt[bin], 1);
    g_perm[pos] = t;
    for (int e = t; e < E; e += NN) {
        int s_ = src[e], d_ = dst[e];
        float nv = sO[s_] * sI[d_];
        int p2 = atomicAdd(&cur[d_], 1);
        g_edge[p2] = make_float2(__int_as_float(s_ * ST), nv);
    }
    if (dI & 1) g_edge[excl + dI] = make_float2(__int_as_float(0), 0.f);
    if (t < 8) g_edge[2560 + t] = make_float2(__int_as_float(0), 0.f);
    g_degO[t] = 0;
    g_degI[t] = 0;
}

// ---------------------------------------------------------------------------
// Octet gather over degree-sorted pairs, edge prefetch pipeline.
// POOL=1: mean-pool partials via shfl.bfly, no stores.
// ---------------------------------------------------------------------------
template <int POOL>
__device__ __forceinline__ void gatherO(const float* __restrict__ bufS,
                                        float* __restrict__ bufD,
                                        const float* __restrict__ sEf,
                                        const int* __restrict__ srow,
                                        const int* __restrict__ sperm,
                                        const float* __restrict__ sbias,
                                        float* __restrict__ pool, int t)
{
    int l = t & 31, w = t >> 5;
    int o = l >> 3, q = l & 7;
    const float* bufq = bufS + 4 * q;
    float4 bv = *(const float4*)(sbias + 4 * q);
    float4 ps = make_float4(0.f, 0.f, 0.f, 0.f);
#pragma unroll
    for (int pp = 0; pp < 4; pp++) {
        int pair = pp * 32 + w * 4 + o;
        int nA = sperm[2 * pair], nB = sperm[2 * pair + 1];
        int jA = srow[nA], eA = srow[nA + 1];
        int jB = srow[nB], eB = srow[nB + 1];
        unsigned long long a0 = 0, a1 = 0, a2 = 0, a3 = 0;
        unsigned long long c0 = 0, c1 = 0, c2 = 0, c3 = 0;
        int iA = jA < eA ? jA : PADJ;
        int iB = jB < eB ? jB : PADJ;
        float4 eA4 = *(const float4*)(sEf + 2 * iA);
        float4 eB4 = *(const float4*)(sEf + 2 * iB);
        while (jA < eA || jB < eB) {
            float4 cA = eA4, cB = eB4;
            jA += 2; jB += 2;
            iA = jA < eA ? jA : PADJ;
            iB = jB < eB ? jB : PADJ;
            eA4 = *(const float4*)(sEf + 2 * iA);       // prefetch next pair
            eB4 = *(const float4*)(sEf + 2 * iB);
            ulonglong2 xA0 = *(const ulonglong2*)(bufq + __float_as_int(cA.x));
            ulonglong2 xA1 = *(const ulonglong2*)(bufq + __float_as_int(cA.z));
            ulonglong2 xB0 = *(const ulonglong2*)(bufq + __float_as_int(cB.x));
            ulonglong2 xB1 = *(const ulonglong2*)(bufq + __float_as_int(cB.z));
            unsigned long long vA0 = dup2(cA.y), vA1 = dup2(cA.w);
            unsigned long long vB0 = dup2(cB.y), vB1 = dup2(cB.w);
            ffma2(a0, vA0, xA0.x); ffma2(a1, vA0, xA0.y);
            ffma2(a2, vA1, xA1.x); ffma2(a3, vA1, xA1.y);
            ffma2(c0, vB0, xB0.x); ffma2(c1, vB0, xB0.y);
            ffma2(c2, vB1, xB1.x); ffma2(c3, vB1, xB1.y);
        }
        float r0, r1, r2, r3, s0, s1, s2, s3;
        unpack2(r0, r1, a0); unpack2(r2, r3, a1);
        unpack2(s0, s1, a2); unpack2(s2, s3, a3);
        float4 hA;
        hA.x = fmaxf(r0 + s0 + bv.x, 0.f);
        hA.y = fmaxf(r1 + s1 + bv.y, 0.f);
        hA.z = fmaxf(r2 + s2 + bv.z, 0.f);
        hA.w = fmaxf(r3 + s3 + bv.w, 0.f);
        unpack2(r0, r1, c0); unpack2(r2, r3, c1);
        unpack2(s0, s1, c2); unpack2(s2, s3, c3);
        float4 hB;
        hB.x = fmaxf(r0 + s0 + bv.x, 0.f);
        hB.y = fmaxf(r1 + s1 + bv.y, 0.f);
        hB.z = fmaxf(r2 + s2 + bv.z, 0.f);
        hB.w = fmaxf(r3 + s3 + bv.w, 0.f);
        if (POOL) {
            ps.x += hA.x + hB.x; ps.y += hA.y + hB.y;
            ps.z += hA.z + hB.z; ps.w += hA.w + hB.w;
        } else {
            *(float4*)(bufD + nA * ST + 4 * q) = hA;
            *(float4*)(bufD + nB * ST + 4 * q) = hB;
        }
    }
    if (POOL) {
#pragma unroll
        for (int m = 8; m <= 16; m <<= 1) {
            ps.x += __shfl_xor_sync(0xffffffffu, ps.x, m);
            ps.y += __shfl_xor_sync(0xffffffffu, ps.y, m);
            ps.z += __shfl_xor_sync(0xffffffffu, ps.z, m);
            ps.w += __shfl_xor_sync(0xffffffffu, ps.w, m);
        }
        if (l < 8) *(float4*)(pool + (w * 8 + q) * 4) = ps;
    }
}

// ---------------------------------------------------------------------------
// Linear: thread = node, 32x32 via packed fma.rn.f32x2.
// ---------------------------------------------------------------------------
__device__ __forceinline__ void linear_phase(const float* __restrict__ bufS,
                                             float* __restrict__ bufD,
                                             const float* __restrict__ W, int t)
{
    float h[HD];
    const float4* hr = (const float4*)(bufS + t * ST);
#pragma unroll
    for (int q = 0; q < 8; q++) {
        float4 v = hr[q];
        h[4*q] = v.x; h[4*q+1] = v.y; h[4*q+2] = v.z; h[4*q+3] = v.w;
    }
    unsigned long long y2[16];
#pragma unroll
    for (int q = 0; q < 16; q++) y2[q] = 0ULL;
#pragma unroll
    for (int k = 0; k < HD; k++) {
        unsigned long long hk = dup2(h[k]);
        const ulonglong2* Wr = (const ulonglong2*)(W + k * HD);
#pragma unroll
        for (int q = 0; q < 8; q++) {
            ulonglong2 wv = Wr[q];
            ffma2(y2[2*q],     hk, wv.x);
            ffma2(y2[2*q + 1], hk, wv.y);
        }
    }
    ulonglong2* out = (ulonglong2*)(bufD + t * ST);
#pragma unroll
    for (int q = 0; q < 8; q++) out[q] = make_ulonglong2(y2[2*q], y2[2*q+1]);
}

// ---------------------------------------------------------------------------
// Main GNN kernel: one CTA per batch element.
// ---------------------------------------------------------------------------
__global__ void __launch_bounds__(NN, 2) gnn_kernel(
    const float* __restrict__ gf, const float* __restrict__ vec,
    const float* __restrict__ W1, const float* __restrict__ b1,
    const float* __restrict__ W2, const float* __restrict__ b2,
    const float* __restrict__ W3, const float* __restrict__ b3,
    const float* __restrict__ We, const float* __restrict__ be)
{
    extern __shared__ float s[];
    float* bufA = s;                         // 9216
    float* bufB = bufA + NN * ST;            // 9216
    float* sEf  = bufB + NN * ST;            // 5136
    int*   srow = (int*)(sEf + 2 * EMAXP);   // 260
    int*   sperm= srow + 260;                // 256
    float* sW1  = (float*)(sperm + 256);     // 192
    float* sW2  = sW1 + 192;                 // 1024
    float* sW3  = sW2 + 1024;                // 1024
    float* sWe  = sW3 + 1024;                // 1024
    float* sb   = sWe + 1024;                // 128
    float* pool = sb + 128;                  // 256
    float* hg   = pool + 256;                // 32

    int t = threadIdx.x;
    int b = blockIdx.x;

    // ---- stage CSR, perm, weights, gf ----
    {
        const float4* ge4 = (const float4*)g_edge;
        float4* se4 = (float4*)sEf;
        for (int i = t; i < EMAXP / 2; i += NN) se4[i] = ge4[i];
        srow[t] = g_rowptr[t];
        sperm[t] = g_perm[t];
        if (t == 0) srow[NN] = g_rowptr[NN];
        if (t < FIN * HD) sW1[t] = W1[t];
        for (int i = t; i < HD * HD; i += NN) {
            sW2[i] = W2[i]; sW3[i] = W3[i]; sWe[i] = We[i];
        }
        if (t < HD) { sb[t] = b1[t]; sb[32+t] = b2[t]; sb[64+t] = b3[t]; sb[96+t] = be[t]; }
        const float4* g4 = (const float4*)(gf + (size_t)b * NN * FIN);
        float4* xb = (float4*)bufB;
#pragma unroll
        for (int i = 0; i < NN * FIN / 4 / NN; i++) xb[t + i * NN] = g4[t + i * NN];
    }
    __syncthreads();

    // ---- phase 0: t0 = x @ W1 -> bufA ----
    {
        float x[FIN];
#pragma unroll
        for (int k = 0; k < FIN; k++) x[k] = bufB[t * FIN + k];
        unsigned long long y2[16];
#pragma unroll
        for (int q = 0; q < 16; q++) y2[q] = 0ULL;
#pragma unroll
        for (int k = 0; k < FIN; k++) {
            unsigned long long xk = dup2(x[k]);
            const ulonglong2* Wr = (const ulonglong2*)(sW1 + k * HD);
#pragma unroll
            for (int q = 0; q < 8; q++) {
                ulonglong2 wv = Wr[q];
                ffma2(y2[2*q], xk, wv.x);
                ffma2(y2[2*q+1], xk, wv.y);
            }
        }
        ulonglong2* row = (ulonglong2*)(bufA + t * ST);
#pragma unroll
        for (int q = 0; q < 8; q++) row[q] = make_ulonglong2(y2[2*q], y2[2*q+1]);
    }
    __syncthreads();

    gatherO<0>(bufA, bufB, sEf, srow, sperm, sb, pool, t);
    __syncthreads();
    linear_phase(bufB, bufA, sW2, t);
    __syncthreads();
    gatherO<0>(bufA, bufB, sEf, srow, sperm, sb + 32, pool, t);
    __syncthreads();
    linear_phase(bufB, bufA, sW3, t);
    __syncthreads();
    gatherO<1>(bufA, bufB, sEf, srow, sperm, sb + 64, pool, t);
    __syncthreads();

    // ---- finish mean pool ----
    if (t < 8) {
        float4 sum = make_float4(0.f, 0.f, 0.f, 0.f);
#pragma unroll
        for (int w = 0; w < 8; w++) {
            float4 v = *(const float4*)(pool + (w * 8 + t) * 4);
            sum.x += v.x; sum.y += v.y; sum.z += v.z; sum.w += v.w;
        }
        const float inv = 1.f / 256.f;
        hg[4*t]   = sum.x * inv; hg[4*t+1] = sum.y * inv;
        hg[4*t+2] = sum.z * inv; hg[4*t+3] = sum.w * inv;
    }
    __syncthreads();

    if (t < HD) {
        float e = sb[96 + t];
#pragma unroll
        for (int k = 0; k < HD; k++)
            e = fmaf(hg[k], sWe[k * HD + t], e);
        g_comb[b * 64 + VECD + t] = e;
    }
    if (t >= 64 && t < 64 + VECD)
        g_comb[b * 64 + (t - 64)] = vec[(size_t)b * VECD + (t - 64)];
}

// ---------------------------------------------------------------------------
// Heads: grid 512 = 32 batch-tiles(32) x 8 col-tiles(64) x 2 heads.
// Thread: 2 batches x 2 col-pairs packed accumulators. ~30KB smem/CTA.
// ---------------------------------------------------------------------------
__global__ void __launch_bounds__(NN) heads_kernel(
    const float* __restrict__ Wpi, const float* __restrict__ bpi,
    const float* __restrict__ Wvf, const float* __restrict__ bvf,
    float* __restrict__ out)
{
    __shared__ __align__(16) float sW[58 * 64];
    __shared__ unsigned long long sC[32 * 58];
    __shared__ float sbias[64];

    int t = threadIdx.x;
    int bt = blockIdx.x & 31;              // batch tile (32 batches)
    int ch = blockIdx.x >> 5;              // 0..15
    int head = ch >> 3;
    int colbase = (ch & 7) * 64;
    const float* W = head ? Wvf : Wpi;
    const float* bias = head ? bvf : bpi;

    for (int i = t; i < 58 * 16; i += NN) {
        int k = i >> 4, c4 = i & 15;
        *(float4*)(sW + k * 64 + c4 * 4) =
            *(const float4*)(W + k * DPI + colbase + c4 * 4);
    }
    if (t < 64) sbias[t] = bias[colbase + t];
    for (int i = t; i < 32 * 58; i += NN) {
        int bb = i / 58, k = i - bb * 58;
        sC[i] = dup2(g_comb[(size_t)(bt * 32 + bb) * 64 + k]);
    }
    __syncthreads();

    int pg = t & 15, bg = t >> 4;
    const unsigned long long* Cb = sC + (bg * 2) * 58;

    unsigned long long acc[2][2];
#pragma unroll
    for (int ss = 0; ss < 2; ss++) {
        int cp = (pg + ss * 16) * 2;
        unsigned long long bp = pack2(sbias[cp], sbias[cp + 1]);
        acc[0][ss] = bp; acc[1][ss] = bp;
    }

#pragma unroll 2
    for (int k = 0; k < 58; k++) {
        unsigned long long wv0 = *(const unsigned long long*)(sW + k * 64 + pg * 2);
        unsigned long long wv1 = *(const unsigned long long*)(sW + k * 64 + (pg + 16) * 2);
        unsigned long long cx0 = Cb[k];
        unsigned long long cx1 = Cb[58 + k];
        ffma2(acc[0][0], cx0, wv0); ffma2(acc[0][1], cx0, wv1);
        ffma2(acc[1][0], cx1, wv0); ffma2(acc[1][1], cx1, wv1);
    }

#pragma unroll
    for (int i = 0; i < 2; i++) {
        int bb = bt * 32 + bg * 2 + i;
        size_t rb = (size_t)head * BB * DPI + (size_t)bb * DPI + colbase;
#pragma unroll
        for (int ss = 0; ss < 2; ss++) {
            float lo, hi;
            unpack2(lo, hi, acc[i][ss]);
            int col = (pg + ss * 16) * 2;
            *(float2*)(out + rb + col) = make_float2(fmaxf(lo, 0.f), fmaxf(hi, 0.f));
        }
    }
}

extern "C" void kernel_launch(void* const* d_in, const int* in_sizes, int n_in,
                              void* d_out, int out_size) {
    const float* gf  = (const float*)d_in[0];
    const float* vec = (const float*)d_in[1];
    const int*   src = (const int*)d_in[2];
    const int*   dst = (const int*)d_in[3];
    const float* W1  = (const float*)d_in[4];
    const float* b1  = (const float*)d_in[5];
    const float* W2  = (const float*)d_in[6];
    const float* b2  = (const float*)d_in[7];
    const float* W3  = (const float*)d_in[8];
    const float* b3  = (const float*)d_in[9];
    const float* We  = (const float*)d_in[10];
    const float* be  = (const float*)d_in[11];
    const float* Wpi = (const float*)d_in[12];
    const float* bpi = (const float*)d_in[13];
    const float* Wvf = (const float*)d_in[14];
    const float* bvf = (const float*)d_in[15];

    int E = in_sizes[2];
    if (E > EMAX) E = EMAX;

    prep1_kernel<<<(E + NN - 1) / NN, NN>>>(src, dst, E);
    prep2_kernel<<<1, NN>>>(src, dst, E);

    // smem floats: 2*9216 + 5136 + 260 + 256 + 192 + 3*1024 + 128 + 256 + 32 = 27764
    int smem = 27764 * (int)sizeof(float);
    cudaFuncSetAttribute(gnn_kernel, cudaFuncAttributeMaxDynamicSharedMemorySize, smem);
    gnn_kernel<<<BB, NN, smem>>>(gf, vec, W1, b1, W2, b2, W3, b3, We, be);
    heads_kernel<<<512, NN>>>(Wpi, bpi, Wvf, bvf, (float*)d_out);
}

// round 10
// speedup vs baseline: 1.9873x; 1.0174x over previous
#include <cuda_runtime.h>

#define NN    256
#define TT    512    // gnn CTA threads
#define FIN   6
#define HD    32
#define VECD  26
#define DPI   512
#define BB    1024
#define EMAX  2304
#define EMAXP 2568   // even-padded capacity + zero slots
#define PADJ  2564   // even pair index at guaranteed-zero edges
#define ST    36     // padded row stride (floats)

__device__ int g_degO[NN];
__device__ int g_degI[NN];
__device__ int g_rowptr[NN + 1];
__device__ int g_perm[NN];
__device__ __align__(16) float2 g_edge[EMAXP];
__device__ float g_comb[BB * 64];

// ---------------------------------------------------------------------------
// packed f32x2 helpers
// ---------------------------------------------------------------------------
__device__ __forceinline__ unsigned long long dup2(float v) {
    unsigned long long r;
    asm("mov.b64 %0, {%1, %1};" : "=l"(r) : "f"(v));
    return r;
}
__device__ __forceinline__ unsigned long long pack2(float lo, float hi) {
    unsigned long long r;
    asm("mov.b64 %0, {%1, %2};" : "=l"(r) : "f"(lo), "f"(hi));
    return r;
}
__device__ __forceinline__ void ffma2(unsigned long long& a, unsigned long long x,
                                      unsigned long long y) {
    asm("fma.rn.f32x2 %0, %1, %2, %0;" : "+l"(a) : "l"(x), "l"(y));
}
__device__ __forceinline__ void unpack2(float& lo, float& hi, unsigned long long v) {
    asm("mov.b64 {%0, %1}, %2;" : "=f"(lo), "=f"(hi) : "l"(v));
}

// ---------------------------------------------------------------------------
// prep1: multi-CTA degree histogram (spread global atomics).
// ---------------------------------------------------------------------------
__global__ void prep1_kernel(const int* __restrict__ src, const int* __restrict__ dst, int E) {
    int e = blockIdx.x * blockDim.x + threadIdx.x;
    if (e < E) {
        atomicAdd(&g_degO[src[e]], 1);
        atomicAdd(&g_degI[dst[e]], 1);
    }
}

// ---------------------------------------------------------------------------
// prep2: scan, norms, scatter CSR, counting-sort nodes by padded degree.
// ---------------------------------------------------------------------------
__global__ void prep2_kernel(const int* __restrict__ src, const int* __restrict__ dst, int E) {
    __shared__ float sO[NN], sI[NN];
    __shared__ int cur[NN];
    __shared__ int wsum[8];
    __shared__ int cnt[128];
    int t = threadIdx.x, lane = t & 31, w = t >> 5;
    int dO = g_degO[t], dI = g_degI[t];
    int dp = (dI + 1) & ~1;
    if (t < 128) cnt[t] = 0;
    int v = dp;
#pragma unroll
    for (int o = 1; o < 32; o <<= 1) {
        int nv_ = __shfl_up_sync(0xffffffffu, v, o);
        if (lane >= o) v += nv_;
    }
    if (lane == 31) wsum[w] = v;
    __syncthreads();
    if (t == 0) {
        int acc = 0;
#pragma unroll
        for (int i = 0; i < 8; i++) { acc += wsum[i]; wsum[i] = acc; }
    }
    int bin = dp >> 1; if (bin > 127) bin = 127;
    atomicAdd(&cnt[bin], 1);
    __syncthreads();
    int excl = (w ? wsum[w - 1] : 0) + v - dp;
    g_rowptr[t] = excl;
    cur[t] = excl;
    if (t == NN - 1) g_rowptr[NN] = excl + dp;
    sO[t] = dO ? rsqrtf((float)dO) : 0.f;
    sI[t] = dI ? rsqrtf((float)dI) : 0.f;
    if (t < 32) {
        int c0 = cnt[t*4], c1 = cnt[t*4+1], c2 = cnt[t*4+2], c3 = cnt[t*4+3];
        int tot = c0 + c1 + c2 + c3;
        int sc = tot;
#pragma unroll
        for (int o = 1; o < 32; o <<= 1) {
            int nv_ = __shfl_up_sync(0xffffffffu, sc, o);
            if (lane >= o) sc += nv_;
        }
        int base = sc - tot;
        cnt[t*4]   = base;
        cnt[t*4+1] = base + c0;
        cnt[t*4+2] = base + c0 + c1;
        cnt[t*4+3] = base + c0 + c1 + c2;
    }
    __syncthreads();
    int pos = atomicAdd(&cnt[bin], 1);
    g_perm[pos] = t;
    for (int e = t; e < E; e += NN) {
        int s_ = src[e], d_ = dst[e];
        float nv = sO[s_] * sI[d_];
        int p2 = atomicAdd(&cur[d_], 1);
        g_edge[p2] = make_float2(__int_as_float(s_ * ST), nv);
    }
    if (dI & 1) g_edge[excl + dI] = make_float2(__int_as_float(0), 0.f);
    if (t < 8) g_edge[2560 + t] = make_float2(__int_as_float(0), 0.f);
    g_degO[t] = 0;
    g_degI[t] = 0;
}

// ---------------------------------------------------------------------------
// Octet gather over degree-sorted pairs, edge prefetch pipeline.
// 16 warps x 2 pairs. POOL=1: mean-pool partials via shfl, no stores.
// ---------------------------------------------------------------------------
template <int POOL>
__device__ __forceinline__ void gatherO(const float* __restrict__ bufS,
                                        float* __restrict__ bufD,
                                        const float* __restrict__ sEf,
                                        const int* __restrict__ srow,
                                        const int* __restrict__ sperm,
                                        const float* __restrict__ sbias,
                                        float* __restrict__ pool, int t)
{
    int l = t & 31, w = t >> 5;
    int o = l >> 3, q = l & 7;
    const float* bufq = bufS + 4 * q;
    float4 bv = *(const float4*)(sbias + 4 * q);
    float4 ps = make_float4(0.f, 0.f, 0.f, 0.f);
#pragma unroll
    for (int pp = 0; pp < 2; pp++) {
        int pair = pp * 64 + w * 4 + o;
        int nA = sperm[2 * pair], nB = sperm[2 * pair + 1];
        int jA = srow[nA], eA = srow[nA + 1];
        int jB = srow[nB], eB = srow[nB + 1];
        unsigned long long a0 = 0, a1 = 0, a2 = 0, a3 = 0;
        unsigned long long c0 = 0, c1 = 0, c2 = 0, c3 = 0;
        int iA = jA < eA ? jA : PADJ;
        int iB = jB < eB ? jB : PADJ;
        float4 eA4 = *(const float4*)(sEf + 2 * iA);
        float4 eB4 = *(const float4*)(sEf + 2 * iB);
        while (jA < eA || jB < eB) {
            float4 cA = eA4, cB = eB4;
            jA += 2; jB += 2;
            iA = jA < eA ? jA : PADJ;
            iB = jB < eB ? jB : PADJ;
            eA4 = *(const float4*)(sEf + 2 * iA);
            eB4 = *(const float4*)(sEf + 2 * iB);
            ulonglong2 xA0 = *(const ulonglong2*)(bufq + __float_as_int(cA.x));
            ulonglong2 xA1 = *(const ulonglong2*)(bufq + __float_as_int(cA.z));
            ulonglong2 xB0 = *(const ulonglong2*)(bufq + __float_as_int(cB.x));
            ulonglong2 xB1 = *(const ulonglong2*)(bufq + __float_as_int(cB.z));
            unsigned long long vA0 = dup2(cA.y), vA1 = dup2(cA.w);
            unsigned long long vB0 = dup2(cB.y), vB1 = dup2(cB.w);
            ffma2(a0, vA0, xA0.x); ffma2(a1, vA0, xA0.y);
            ffma2(a2, vA1, xA1.x); ffma2(a3, vA1, xA1.y);
            ffma2(c0, vB0, xB0.x); ffma2(c1, vB0, xB0.y);
            ffma2(c2, vB1, xB1.x); ffma2(c3, vB1, xB1.y);
        }
        float r0, r1, r2, r3, s0, s1, s2, s3;
        unpack2(r0, r1, a0); unpack2(r2, r3, a1);
        unpack2(s0, s1, a2); unpack2(s2, s3, a3);
        float4 hA;
        hA.x = fmaxf(r0 + s0 + bv.x, 0.f);
        hA.y = fmaxf(r1 + s1 + bv.y, 0.f);
        hA.z = fmaxf(r2 + s2 + bv.z, 0.f);
        hA.w = fmaxf(r3 + s3 + bv.w, 0.f);
        unpack2(r0, r1, c0); unpack2(r2, r3, c1);
        unpack2(s0, s1, c2); unpack2(s2, s3, c3);
        float4 hB;
        hB.x = fmaxf(r0 + s0 + bv.x, 0.f);
        hB.y = fmaxf(r1 + s1 + bv.y, 0.f);
        hB.z = fmaxf(r2 + s2 + bv.z, 0.f);
        hB.w = fmaxf(r3 + s3 + bv.w, 0.f);
        if (POOL) {
            ps.x += hA.x + hB.x; ps.y += hA.y + hB.y;
            ps.z += hA.z + hB.z; ps.w += hA.w + hB.w;
        } else {
            *(float4*)(bufD + nA * ST + 4 * q) = hA;
            *(float4*)(bufD + nB * ST + 4 * q) = hB;
        }
    }
    if (POOL) {
#pragma unroll
        for (int m = 8; m <= 16; m <<= 1) {
            ps.x += __shfl_xor_sync(0xffffffffu, ps.x, m);
            ps.y += __shfl_xor_sync(0xffffffffu, ps.y, m);
            ps.z += __shfl_xor_sync(0xffffffffu, ps.z, m);
            ps.w += __shfl_xor_sync(0xffffffffu, ps.w, m);
        }
        if (l < 8) *(float4*)(pool + (w * 8 + q) * 4) = ps;
    }
}

// ---------------------------------------------------------------------------
// Linear: thread = (node t>>1, feature-half t&1); 16 outputs via f32x2.
// ---------------------------------------------------------------------------
__device__ __forceinline__ void linear_phase(const float* __restrict__ bufS,
                                             float* __restrict__ bufD,
                                             const float* __restrict__ W, int t)
{
    int n = t >> 1, fo = (t & 1) * 16;
    float h[HD];
    const float4* hr = (const float4*)(bufS + n * ST);
#pragma unroll
    for (int q = 0; q < 8; q++) {
        float4 v = hr[q];
        h[4*q] = v.x; h[4*q+1] = v.y; h[4*q+2] = v.z; h[4*q+3] = v.w;
    }
    unsigned long long y2[8];
#pragma unroll
    for (int q = 0; q < 8; q++) y2[q] = 0ULL;
#pragma unroll
    for (int k = 0; k < HD; k++) {
        unsigned long long hk = dup2(h[k]);
        const ulonglong2* Wr = (const ulonglong2*)(W + k * HD + fo);
#pragma unroll
        for (int q = 0; q < 4; q++) {
            ulonglong2 wv = Wr[q];
            ffma2(y2[2*q],     hk, wv.x);
            ffma2(y2[2*q + 1], hk, wv.y);
        }
    }
    ulonglong2* out = (ulonglong2*)(bufD + n * ST + fo);
#pragma unroll
    for (int q = 0; q < 4; q++) out[q] = make_ulonglong2(y2[2*q], y2[2*q+1]);
}

// ---------------------------------------------------------------------------
// Main GNN kernel: one CTA (512 threads) per batch element.
// ---------------------------------------------------------------------------
__global__ void __launch_bounds__(TT, 2) gnn_kernel(
    const float* __restrict__ gf, const float* __restrict__ vec,
    const float* __restrict__ W1, const float* __restrict__ b1,
    const float* __restrict__ W2, const float* __restrict__ b2,
    const float* __restrict__ W3, const float* __restrict__ b3,
    const float* __restrict__ We, const float* __restrict__ be)
{
    extern __shared__ float s[];
    float* bufA = s;                         // 9216
    float* bufB = bufA + NN * ST;            // 9216
    float* sEf  = bufB + NN * ST;            // 5136
    int*   srow = (int*)(sEf + 2 * EMAXP);   // 260
    int*   sperm= srow + 260;                // 256
    float* sW1  = (float*)(sperm + 256);     // 192
    float* sW2  = sW1 + 192;                 // 1024
    float* sW3  = sW2 + 1024;                // 1024
    float* sWe  = sW3 + 1024;                // 1024
    float* sb   = sWe + 1024;                // 128
    float* pool = sb + 128;                  // 512
    float* hg   = pool + 512;                // 32

    int t = threadIdx.x;
    int b = blockIdx.x;

    // ---- stage CSR, perm, weights, gf ----
    {
        const float4* ge4 = (const float4*)g_edge;
        float4* se4 = (float4*)sEf;
        for (int i = t; i < EMAXP / 2; i += TT) se4[i] = ge4[i];
        if (t < NN) { srow[t] = g_rowptr[t]; sperm[t] = g_perm[t]; }
        if (t == 0) srow[NN] = g_rowptr[NN];
        if (t < FIN * HD) sW1[t] = W1[t];
        for (int i = t; i < HD * HD; i += TT) {
            sW2[i] = W2[i]; sW3[i] = W3[i]; sWe[i] = We[i];
        }
        if (t < HD) { sb[t] = b1[t]; sb[32+t] = b2[t]; sb[64+t] = b3[t]; sb[96+t] = be[t]; }
        const float4* g4 = (const float4*)(gf + (size_t)b * NN * FIN);
        float4* xb = (float4*)bufB;
        if (t < NN * FIN / 4) xb[t] = g4[t];
    }
    __syncthreads();

    // ---- phase 0: t0 = x @ W1 -> bufA (node t>>1, 16 features) ----
    {
        int n = t >> 1, fo = (t & 1) * 16;
        float x[FIN];
#pragma unroll
        for (int k = 0; k < FIN; k++) x[k] = bufB[n * FIN + k];
        unsigned long long y2[8];
#pragma unroll
        for (int q = 0; q < 8; q++) y2[q] = 0ULL;
#pragma unroll
        for (int k = 0; k < FIN; k++) {
            unsigned long long xk = dup2(x[k]);
            const ulonglong2* Wr = (const ulonglong2*)(sW1 + k * HD + fo);
#pragma unroll
            for (int q = 0; q < 4; q++) {
                ulonglong2 wv = Wr[q];
                ffma2(y2[2*q], xk, wv.x);
                ffma2(y2[2*q+1], xk, wv.y);
            }
        }
        ulonglong2* row = (ulonglong2*)(bufA + n * ST + fo);
#pragma unroll
        for (int q = 0; q < 4; q++) row[q] = make_ulonglong2(y2[2*q], y2[2*q+1]);
    }
    __syncthreads();

    gatherO<0>(bufA, bufB, sEf, srow, sperm, sb, pool, t);
    __syncthreads();
    linear_phase(bufB, bufA, sW2, t);
    __syncthreads();
    gatherO<0>(bufA, bufB, sEf, srow, sperm, sb + 32, pool, t);
    __syncthreads();
    linear_phase(bufB, bufA, sW3, t);
    __syncthreads();
    gatherO<1>(bufA, bufB, sEf, srow, sperm, sb + 64, pool, t);
    __syncthreads();

    // ---- finish mean pool (16 warps' partials) ----
    if (t < 8) {
        float4 sum = make_float4(0.f, 0.f, 0.f, 0.f);
#pragma unroll
        for (int w = 0; w < 16; w++) {
            float4 v = *(const float4*)(pool + (w * 8 + t) * 4);
            sum.x += v.x; sum.y += v.y; sum.z += v.z; sum.w += v.w;
        }
        const float inv = 1.f / 256.f;
        hg[4*t]   = sum.x * inv; hg[4*t+1] = sum.y * inv;
        hg[4*t+2] = sum.z * inv; hg[4*t+3] = sum.w * inv;
    }
    __syncthreads();

    if (t < HD) {
        float e = sb[96 + t];
#pragma unroll
        for (int k = 0; k < HD; k++)
            e = fmaf(hg[k], sWe[k * HD + t], e);
        g_comb[b * 64 + VECD + t] = e;
    }
    if (t >= 64 && t < 64 + VECD)
        g_comb[b * 64 + (t - 64)] = vec[(size_t)b * VECD + (t - 64)];
}

// ---------------------------------------------------------------------------
// Heads: grid 128 = 16 batch-tiles(64) x 4 col-tiles(128) x 2 heads.
// Thread: 8 batches (4 packed pairs) x 4 cols = 16 f32x2 accumulators.
// W staged pre-duplicated (dup2), C staged as batch-pairs (pack2).
// Lane-interleaved W cols (2pg / 64+2pg) -> conflict-free LDS.128.
// ---------------------------------------------------------------------------
__global__ void __launch_bounds__(NN) heads_kernel(
    const float* __restrict__ Wpi, const float* __restrict__ bpi,
    const float* __restrict__ Wvf, const float* __restrict__ bvf,
    float* __restrict__ out)
{
    extern __shared__ unsigned long long hs[];
    unsigned long long* sWd = hs;                 // 58*128 dup pairs
    unsigned long long* sCp = sWd + 58 * 128;     // 58*32 batch pairs
    float* sbias = (float*)(sCp + 58 * 32);       // 128

    int t = threadIdx.x;
    int bt = blockIdx.x & 15;
    int ch = blockIdx.x >> 4;          // 0..7
    int head = ch >> 2;
    int colbase = (ch & 3) * 128;
    const float* W = head ? Wvf : Wpi;
    const float* bias = head ? bvf : bpi;
    int b0 = bt * 64;

    for (int i = t; i < 58 * 128; i += NN) {
        int k = i >> 7, c = i & 127;
        sWd[i] = dup2(W[k * DPI + colbase + c]);
    }
    if (t < 128) sbias[t] = bias[colbase + t];
    for (int i = t; i < 58 * 32; i += NN) {
        int k = i >> 5, p = i & 31;
        const float* cb = g_comb + (size_t)(b0 + 2 * p) * 64 + k;
        sCp[i] = pack2(cb[0], cb[64]);
    }
    __syncthreads();

    int pg = t & 31, bg = t >> 5;
    // thread cols: {2pg, 2pg+1, 64+2pg, 64+2pg+1}; batch pairs: bg*4 .. bg*4+3
    unsigned long long acc[4][4];
#pragma unroll
    for (int c = 0; c < 4; c++) {
        int col = (c < 2) ? (2 * pg + c) : (64 + 2 * pg + (c - 2));
        unsigned long long bd = dup2(sbias[col]);
#pragma unroll
        for (int p = 0; p < 4; p++) acc[p][c] = bd;
    }

#pragma unroll 2
    for (int k = 0; k < 58; k++) {
        ulonglong2 wlo = *(const ulonglong2*)(sWd + k * 128 + 2 * pg);
        ulonglong2 whi = *(const ulonglong2*)(sWd + k * 128 + 64 + 2 * pg);
        ulonglong2 c01 = *(const ulonglong2*)(sCp + k * 32 + bg * 4);
        ulonglong2 c23 = *(const ulonglong2*)(sCp + k * 32 + bg * 4 + 2);
        unsigned long long wd[4] = {wlo.x, wlo.y, whi.x, whi.y};
        unsigned long long cp[4] = {c01.x, c01.y, c23.x, c23.y};
#pragma unroll
        for (int p = 0; p < 4; p++) {
#pragma unroll
            for (int c = 0; c < 4; c++) ffma2(acc[p][c], cp[p], wd[c]);
        }
    }

#pragma unroll
    for (int p = 0; p < 4; p++) {
        int blo = b0 + 2 * (bg * 4 + p);
        float lo0, hi0, lo1, hi1, lo2, hi2, lo3, hi3;
        unpack2(lo0, hi0, acc[p][0]); unpack2(lo1, hi1, acc[p][1]);
        unpack2(lo2, hi2, acc[p][2]); unpack2(lo3, hi3, acc[p][3]);
        size_t base = (size_t)head * BB * DPI + (size_t)blo * DPI + colbase;
        *(float2*)(out + base + 2 * pg) =
            make_float2(fmaxf(lo0, 0.f), fmaxf(lo1, 0.f));
        *(float2*)(out + base + 64 + 2 * pg) =
            make_float2(fmaxf(lo2, 0.f), fmaxf(lo3, 0.f));
        *(float2*)(out + base + DPI + 2 * pg) =
            make_float2(fmaxf(hi0, 0.f), fmaxf(hi1, 0.f));
        *(float2*)(out + base + DPI + 64 + 2 * pg) =
            make_float2(fmaxf(hi2, 0.f), fmaxf(hi3, 0.f));
    }
}

extern "C" void kernel_launch(void* const* d_in, const int* in_sizes, int n_in,
                              void* d_out, int out_size) {
    const float* gf  = (const float*)d_in[0];
    const float* vec = (const float*)d_in[1];
    const int*   src = (const int*)d_in[2];
    const int*   dst = (const int*)d_in[3];
    const float* W1  = (const float*)d_in[4];
    const float* b1  = (const float*)d_in[5];
    const float* W2  = (const float*)d_in[6];
    const float* b2  = (const float*)d_in[7];
    const float* W3  = (const float*)d_in[8];
    const float* b3  = (const float*)d_in[9];
    const float* We  = (const float*)d_in[10];
    const float* be  = (const float*)d_in[11];
    const float* Wpi = (const float*)d_in[12];
    const float* bpi = (const float*)d_in[13];
    const float* Wvf = (const float*)d_in[14];
    const float* bvf = (const float*)d_in[15];

    int E = in_sizes[2];
    if (E > EMAX) E = EMAX;

    prep1_kernel<<<(E + NN - 1) / NN, NN>>>(src, dst, E);
    prep2_kernel<<<1, NN>>>(src, dst, E);

    // gnn smem floats: 2*9216 + 5136 + 260 + 256 + 192 + 3*1024 + 128 + 512 + 32 = 28020
    int smem = 28020 * (int)sizeof(float);
    cudaFuncSetAttribute(gnn_kernel, cudaFuncAttributeMaxDynamicSharedMemorySize, smem);
    gnn_kernel<<<BB, TT, smem>>>(gf, vec, W1, b1, W2, b2, W3, b3, We, be);

    int hsmem = (58 * 128 + 58 * 32) * 8 + 128 * 4;   // 74752 + 512
    cudaFuncSetAttribute(heads_kernel, cudaFuncAttributeMaxDynamicSharedMemorySize, hsmem);
    heads_kernel<<<128, NN, hsmem>>>(Wpi, bpi, Wvf, bvf, (float*)d_out);
}